// round 12
// baseline (speedup 1.0000x reference)
#include <cuda_runtime.h>
#include <cuda_fp16.h>
#include <cstdint>

// ---------------------------------------------------------------------------
// Problem constants (fixed by the dataset)
// ---------------------------------------------------------------------------
#define N_NODES 100000
#define N_EDGES 1600000
#define D_IN    256
#define D_HID   512
#define D_OUT   48
#define K_STEPS 10
#define ALPHA   0.1f

#define NBLK_NODES ((N_NODES + 255) / 256)   // 391
#define W1_ELEMS  (D_IN * D_HID)             // 131072
#define N_BUCKET  64
#define NBLK_G    (N_NODES / 32)             // 3125 (exact: 100000 = 32*3125)

// ---------------------------------------------------------------------------
// Scratch (static __device__ arrays; no allocation allowed)
// ---------------------------------------------------------------------------
__device__ __align__(16) float g_hid[(size_t)N_NODES * D_HID];   // tf32-rounded
__device__ __align__(16) float g_h[(size_t)N_NODES * D_OUT];
__device__ __align__(16) float g_w1r[W1_ELEMS];                  // tf32-rounded W1
__device__ __align__(16) __half2 g_zA[(size_t)N_NODES * (D_OUT / 2)];
__device__ __align__(16) __half2 g_zB[(size_t)N_NODES * (D_OUT / 2)];
__device__ float g_dinv[N_NODES];
__device__ int   g_deg[N_NODES];
__device__ int   g_cursor[N_NODES];
__device__ int   g_rowptr[N_NODES + 1];
__device__ int   g_bsum[NBLK_NODES];
__device__ int   g_bpre[NBLK_NODES];
__device__ int   g_bucket[N_BUCKET];
__device__ int   g_bstart[N_BUCKET];
__device__ int   g_bcur[N_BUCKET];
__device__ int   g_perm[N_NODES];     // rank-interleaved degree-balanced map
__device__ int   g_src[N_EDGES];
__device__ int   g_dst[N_EDGES];
__device__ int   g_csri[N_EDGES];     // CSR: src index only (norm folded into z)

// ---------------------------------------------------------------------------
// mma helpers
// ---------------------------------------------------------------------------
__device__ __forceinline__ uint32_t f2tf32(float f) {
    uint32_t u;
    asm("cvt.rna.tf32.f32 %0, %1;" : "=r"(u) : "f"(f));
    return u;
}

__device__ __forceinline__ void mma_tf32(float* c,
                                         uint32_t a0, uint32_t a1,
                                         uint32_t a2, uint32_t a3,
                                         uint32_t b0, uint32_t b1) {
    asm volatile(
        "mma.sync.aligned.m16n8k8.row.col.f32.tf32.tf32.f32 "
        "{%0,%1,%2,%3}, {%4,%5,%6,%7}, {%8,%9}, {%0,%1,%2,%3};"
        : "+f"(c[0]), "+f"(c[1]), "+f"(c[2]), "+f"(c[3])
        : "r"(a0), "r"(a1), "r"(a2), "r"(a3), "r"(b0), "r"(b1));
}

#define CP_ASYNC_16(dst_u32, src_ptr) \
    asm volatile("cp.async.cg.shared.global [%0], [%1], 16;" \
                 :: "r"(dst_u32), "l"(src_ptr))
#define CP_COMMIT() asm volatile("cp.async.commit_group;")
#define CP_WAIT(N)  asm volatile("cp.async.wait_group %0;" :: "n"(N))

// ---------------------------------------------------------------------------
// GEMM1: g_hid = relu(x @ W1 + b1), tf32 tensor cores. (R9 version: fp32 out)
// ---------------------------------------------------------------------------
#define AS_STRIDE 20
#define BS_STRIDE 136
#define AS_STAGE (128 * AS_STRIDE)
#define BS_STAGE (16 * BS_STRIDE)
#define G1_SMEM ((3 * AS_STAGE + 3 * BS_STAGE) * 4)   // 56832 bytes
#define N_CHUNK (D_IN / 16)                 // 16

__global__ __launch_bounds__(256, 2) void gemm1_tc_kernel(
    const float* __restrict__ A,    // [M, 256]
    const float* __restrict__ bias, // [512]
    int M)
{
    extern __shared__ float smem[];
    float* AsB = smem;
    float* BsB = smem + 3 * AS_STAGE;

    const int tid = threadIdx.x;
    const int bn = blockIdx.x * 128;
    const int bm = blockIdx.y * 128;

    const int wid = tid >> 5;
    const int lane = tid & 31;
    const int g = lane >> 2;
    const int t = lane & 3;
    const int wm = wid & 1;
    const int wn = wid >> 1;

    float acc[4][4][4];
#pragma unroll
    for (int i = 0; i < 4; i++)
#pragma unroll
        for (int j = 0; j < 4; j++)
#pragma unroll
            for (int q = 0; q < 4; q++) acc[i][j][q] = 0.0f;

    uint32_t aDst[2], bDst[2];
    const float* aSrc[2];
    const float* bSrc[2];
    {
        const uint32_t asBase = (uint32_t)__cvta_generic_to_shared(AsB);
        const uint32_t bsBase = (uint32_t)__cvta_generic_to_shared(BsB);
#pragma unroll
        for (int q = 0; q < 2; q++) {
            const int idx = tid + 256 * q;
            const int ar = idx >> 2;
            const int ac = (idx & 3) * 4;
            aDst[q] = asBase + (ar * AS_STRIDE + ac) * 4;
            const int gr = min(bm + ar, M - 1);
            aSrc[q] = A + (size_t)gr * D_IN + ac;
            const int br = idx >> 5;
            const int bc = (idx & 31) * 4;
            bDst[q] = bsBase + (br * BS_STRIDE + bc) * 4;
            bSrc[q] = g_w1r + (size_t)br * D_HID + bn + bc;
        }
    }

#pragma unroll
    for (int q = 0; q < 2; q++) {
        CP_ASYNC_16(aDst[q], aSrc[q]);
        CP_ASYNC_16(bDst[q], bSrc[q]);
    }
    CP_COMMIT();
#pragma unroll
    for (int q = 0; q < 2; q++) {
        CP_ASYNC_16(aDst[q] + AS_STAGE * 4, aSrc[q] + 16);
        CP_ASYNC_16(bDst[q] + BS_STAGE * 4, bSrc[q] + (size_t)16 * D_HID);
    }
    CP_COMMIT();

    int stC = 0;
    for (int ch = 0; ch < N_CHUNK; ch++) {
        if (ch < N_CHUNK - 1) { CP_WAIT(1); } else { CP_WAIT(0); }
        __syncthreads();

        const float* As = AsB + stC * AS_STAGE;
        const float* Bs = BsB + stC * BS_STAGE;
#pragma unroll
        for (int ks = 0; ks < 2; ks++) {
            const int kb = ks * 8;
            uint32_t af[4][4], bf[4][2];
#pragma unroll
            for (int i = 0; i < 4; i++) {
                const int m = wm * 64 + i * 16 + g;
                af[i][0] = f2tf32(As[m * AS_STRIDE + kb + t]);
                af[i][1] = f2tf32(As[(m + 8) * AS_STRIDE + kb + t]);
                af[i][2] = f2tf32(As[m * AS_STRIDE + kb + t + 4]);
                af[i][3] = f2tf32(As[(m + 8) * AS_STRIDE + kb + t + 4]);
            }
#pragma unroll
            for (int j = 0; j < 4; j++) {
                const int n = wn * 32 + j * 8 + g;
                bf[j][0] = __float_as_uint(Bs[(kb + t) * BS_STRIDE + n]);
                bf[j][1] = __float_as_uint(Bs[(kb + t + 4) * BS_STRIDE + n]);
            }
#pragma unroll
            for (int i = 0; i < 4; i++)
#pragma unroll
                for (int j = 0; j < 4; j++)
                    mma_tf32(acc[i][j], af[i][0], af[i][1], af[i][2], af[i][3],
                             bf[j][0], bf[j][1]);
        }

        if (ch + 2 < N_CHUNK) {
            const int stP = (stC + 2 >= 3) ? stC - 1 : stC + 2;
            const int ko = (ch + 2) * 16;
#pragma unroll
            for (int q = 0; q < 2; q++) {
                CP_ASYNC_16(aDst[q] + stP * AS_STAGE * 4, aSrc[q] + ko);
                CP_ASYNC_16(bDst[q] + stP * BS_STAGE * 4, bSrc[q] + (size_t)ko * D_HID);
            }
            CP_COMMIT();
        }
        stC = (stC + 1 == 3) ? 0 : stC + 1;
    }

    // epilogue: bias + relu + round to tf32 (GEMM2 consumes without converting)
#pragma unroll
    for (int i = 0; i < 4; i++) {
        const int r0 = bm + wm * 64 + i * 16 + g;
        const int r1 = r0 + 8;
#pragma unroll
        for (int j = 0; j < 4; j++) {
            const int gc = bn + wn * 32 + j * 8 + 2 * t;
            const float bz0 = __ldg(bias + gc);
            const float bz1 = __ldg(bias + gc + 1);
            if (r0 < M) {
                float2 v;
                v.x = __uint_as_float(f2tf32(fmaxf(acc[i][j][0] + bz0, 0.f)));
                v.y = __uint_as_float(f2tf32(fmaxf(acc[i][j][1] + bz1, 0.f)));
                *(float2*)(g_hid + (size_t)r0 * D_HID + gc) = v;
            }
            if (r1 < M) {
                float2 v;
                v.x = __uint_as_float(f2tf32(fmaxf(acc[i][j][2] + bz0, 0.f)));
                v.y = __uint_as_float(f2tf32(fmaxf(acc[i][j][3] + bz1, 0.f)));
                *(float2*)(g_hid + (size_t)r1 * D_HID + gc) = v;
            }
        }
    }
}

// ---------------------------------------------------------------------------
// GEMM2 (R9 version): h = g_hid @ W2 + b2 (tf32; g_hid already tf32 bits).
// Epilogue: g_h = h (fp32); zbuf = half2(dinv * h).
// ---------------------------------------------------------------------------
#define G1_STRIDE 136
#define G2_BSTRIDE 56

__global__ __launch_bounds__(256) void gemm2_tc_kernel(
    const float* __restrict__ W2,   // [512, 48]
    const float* __restrict__ bias, // [48]
    __half2* __restrict__ zbuf,     // [M, 24]
    int M)
{
    __shared__ __align__(16) uint32_t As2[32][G1_STRIDE];
    __shared__ __align__(16) uint32_t Bs2[32][G2_BSTRIDE];

    const int tid = threadIdx.x;
    const int bm = blockIdx.x * 128;

    const int wid = tid >> 5;
    const int lane = tid & 31;
    const int g = lane >> 2;
    const int t = lane & 3;
    const int wm = wid & 3;
    const int wn = wid >> 2;

    const int aRow = tid >> 1;
    const int aColBase = (tid & 1) * 16;

    float acc[2][3][4];
#pragma unroll
    for (int i = 0; i < 2; i++)
#pragma unroll
        for (int j = 0; j < 3; j++)
#pragma unroll
            for (int q = 0; q < 4; q++) acc[i][j][q] = 0.0f;

    const int gr = bm + aRow;
    float4 aPre[4];
    float2 bPre[3];

#pragma unroll
    for (int j = 0; j < 4; j++)
        aPre[j] = (gr < M) ? *(const float4*)(g_hid + (size_t)gr * D_HID + aColBase + 4 * j)
                           : make_float4(0.f, 0.f, 0.f, 0.f);
#pragma unroll
    for (int j = 0; j < 3; j++) {
        const int idx = tid + 256 * j;
        const int r = idx / 24;
        const int c = (idx % 24) * 2;
        bPre[j] = *(const float2*)(W2 + (size_t)r * D_OUT + c);
    }

    for (int k0 = 0; k0 < D_HID; k0 += 32) {
#pragma unroll
        for (int j = 0; j < 4; j++) {
            const int c = aColBase + 4 * j;
            As2[c + 0][aRow] = __float_as_uint(aPre[j].x);
            As2[c + 1][aRow] = __float_as_uint(aPre[j].y);
            As2[c + 2][aRow] = __float_as_uint(aPre[j].z);
            As2[c + 3][aRow] = __float_as_uint(aPre[j].w);
        }
#pragma unroll
        for (int j = 0; j < 3; j++) {
            const int idx = tid + 256 * j;
            const int r = idx / 24;
            const int c = (idx % 24) * 2;
            Bs2[r][c + 0] = f2tf32(bPre[j].x);
            Bs2[r][c + 1] = f2tf32(bPre[j].y);
        }
        __syncthreads();

        if (k0 + 32 < D_HID) {
#pragma unroll
            for (int j = 0; j < 4; j++)
                aPre[j] = (gr < M) ? *(const float4*)(g_hid + (size_t)gr * D_HID + k0 + 32 + aColBase + 4 * j)
                                   : make_float4(0.f, 0.f, 0.f, 0.f);
#pragma unroll
            for (int j = 0; j < 3; j++) {
                const int idx = tid + 256 * j;
                const int r = idx / 24;
                const int c = (idx % 24) * 2;
                bPre[j] = *(const float2*)(W2 + (size_t)(k0 + 32 + r) * D_OUT + c);
            }
        }

#pragma unroll
        for (int ks = 0; ks < 4; ks++) {
            const int kb = ks * 8;
            uint32_t af[2][4], bf[3][2];
#pragma unroll
            for (int i = 0; i < 2; i++) {
                const int m = wm * 32 + i * 16 + g;
                af[i][0] = As2[kb + t][m];
                af[i][1] = As2[kb + t][m + 8];
                af[i][2] = As2[kb + t + 4][m];
                af[i][3] = As2[kb + t + 4][m + 8];
            }
#pragma unroll
            for (int j = 0; j < 3; j++) {
                const int n = wn * 24 + j * 8 + g;
                bf[j][0] = Bs2[kb + t][n];
                bf[j][1] = Bs2[kb + t + 4][n];
            }
#pragma unroll
            for (int i = 0; i < 2; i++)
#pragma unroll
                for (int j = 0; j < 3; j++)
                    mma_tf32(acc[i][j], af[i][0], af[i][1], af[i][2], af[i][3],
                             bf[j][0], bf[j][1]);
        }
        __syncthreads();
    }

#pragma unroll
    for (int i = 0; i < 2; i++) {
        const int r0 = bm + wm * 32 + i * 16 + g;
        const int r1 = r0 + 8;
        const float dv0 = (r0 < M) ? __ldg(g_dinv + r0) : 0.f;
        const float dv1 = (r1 < M) ? __ldg(g_dinv + r1) : 0.f;
#pragma unroll
        for (int j = 0; j < 3; j++) {
            const int gc = wn * 24 + j * 8 + 2 * t;
            const float bz0 = __ldg(bias + gc);
            const float bz1 = __ldg(bias + gc + 1);
            if (r0 < M) {
                float2 v = make_float2(acc[i][j][0] + bz0, acc[i][j][1] + bz1);
                *(float2*)(g_h + (size_t)r0 * D_OUT + gc) = v;
                zbuf[(size_t)r0 * (D_OUT / 2) + gc / 2] =
                    __float22half2_rn(make_float2(dv0 * v.x, dv0 * v.y));
            }
            if (r1 < M) {
                float2 v = make_float2(acc[i][j][2] + bz0, acc[i][j][3] + bz1);
                *(float2*)(g_h + (size_t)r1 * D_OUT + gc) = v;
                zbuf[(size_t)r1 * (D_OUT / 2) + gc / 2] =
                    __float22half2_rn(make_float2(dv1 * v.x, dv1 * v.y));
            }
        }
    }
}

// ---------------------------------------------------------------------------
// Graph preprocessing
// ---------------------------------------------------------------------------
__global__ void convert_idx_kernel(const void* __restrict__ ei_raw) {
    const int* p32 = (const int*)ei_raw;
    bool is64 = true;
#pragma unroll
    for (int i = 0; i < 8; i++) is64 = is64 && (p32[2 * i + 1] == 0);

    int e = blockIdx.x * blockDim.x + threadIdx.x;
    if (e >= N_EDGES) return;
    int s, d;
    if (is64) {
        const long long* p64 = (const long long*)ei_raw;
        s = (int)p64[e];
        d = (int)p64[(size_t)N_EDGES + e];
    } else {
        s = p32[e];
        d = p32[(size_t)N_EDGES + e];
    }
    s = min(max(s, 0), N_NODES - 1);
    d = min(max(d, 0), N_NODES - 1);
    g_src[e] = s;
    g_dst[e] = d;
}

// Fused: zero deg/cursor/buckets + pre-round W1 to tf32.
__global__ void prep_kernel(const float* __restrict__ W1) {
    int i = blockIdx.x * blockDim.x + threadIdx.x;
    if (i < N_NODES) { g_deg[i] = 0; g_cursor[i] = 0; }
    if (i < N_BUCKET) { g_bucket[i] = 0; g_bcur[i] = 0; }
    if (i < W1_ELEMS) g_w1r[i] = __uint_as_float(f2tf32(W1[i]));
}

__global__ void deg_acc_kernel() {
    int e = blockIdx.x * blockDim.x + threadIdx.x;
    if (e < N_EDGES) atomicAdd(&g_deg[g_dst[e]], 1);
}

__global__ __launch_bounds__(256) void blocksum_dinv_kernel() {
    __shared__ int swarp[8];
    const int t = threadIdx.x;
    const int i = blockIdx.x * 256 + t;
    int d = 0;
    if (i < N_NODES) {
        d = g_deg[i];
        g_dinv[i] = rsqrtf((float)(d + 1));   // +1 self-loop
    }
    int v = d;
#pragma unroll
    for (int o = 16; o > 0; o >>= 1) v += __shfl_down_sync(0xffffffffu, v, o);
    if ((t & 31) == 0) swarp[t >> 5] = v;
    __syncthreads();
    if (t == 0) {
        int s = 0;
#pragma unroll
        for (int w = 0; w < 8; w++) s += swarp[w];
        g_bsum[blockIdx.x] = s;
    }
}

__global__ __launch_bounds__(512) void scan_bsums_kernel() {
    __shared__ int sh[512];
    const int t = threadIdx.x;
    sh[t] = (t < NBLK_NODES) ? g_bsum[t] : 0;
    __syncthreads();
#pragma unroll
    for (int off = 1; off < 512; off <<= 1) {
        int v = (t >= off) ? sh[t - off] : 0;
        __syncthreads();
        sh[t] += v;
        __syncthreads();
    }
    if (t < NBLK_NODES) g_bpre[t] = (t == 0) ? 0 : sh[t - 1];
}

__global__ __launch_bounds__(256) void rowptr_kernel() {
    __shared__ int swarp[8];
    const int t = threadIdx.x;
    const int i = blockIdx.x * 256 + t;
    const int lane = t & 31;
    const int w = t >> 5;

    int d = (i < N_NODES) ? g_deg[i] : 0;
    int v = d;
#pragma unroll
    for (int o = 1; o < 32; o <<= 1) {
        int n = __shfl_up_sync(0xffffffffu, v, o);
        if (lane >= o) v += n;
    }
    if (lane == 31) swarp[w] = v;
    __syncthreads();
    if (t == 0) {
        int r = 0;
#pragma unroll
        for (int k = 0; k < 8; k++) { int tmp = swarp[k]; swarp[k] = r; r += tmp; }
    }
    __syncthreads();

    const int excl = g_bpre[blockIdx.x] + swarp[w] + (v - d);
    if (i < N_NODES) {
        g_rowptr[i] = excl;
        if (i == N_NODES - 1) g_rowptr[N_NODES] = excl + d;
    }
}

// Degree histogram (64 buckets).
__global__ __launch_bounds__(256) void hist_kernel() {
    __shared__ int sh[N_BUCKET];
    const int t = threadIdx.x;
    if (t < N_BUCKET) sh[t] = 0;
    __syncthreads();
    const int i = blockIdx.x * 256 + t;
    if (i < N_NODES) atomicAdd(&sh[min(g_deg[i], N_BUCKET - 1)], 1);
    __syncthreads();
    if (t < N_BUCKET && sh[t] > 0) atomicAdd(&g_bucket[t], sh[t]);
}

// Exclusive scan of 64 bucket counts (1 warp, 2 per thread).
__global__ __launch_bounds__(32) void bucket_scan_kernel() {
    const int t = threadIdx.x;
    const int c0 = g_bucket[2 * t];
    const int c1 = g_bucket[2 * t + 1];
    int s = c0 + c1;
#pragma unroll
    for (int o = 1; o < 32; o <<= 1) {
        int n = __shfl_up_sync(0xffffffffu, s, o);
        if (t >= o) s += n;
    }
    const int excl = s - (c0 + c1);
    g_bstart[2 * t] = excl;
    g_bstart[2 * t + 1] = excl + c0;
}

// Scatter: sorted rank r -> gid = (r % 3125)*32 + r/3125.
// Warps get 4 adjacent ranks (spaced 3125 apart in sorted order -> near-equal
// degree); blocks sample the whole degree distribution uniformly.
__global__ void perm_scatter_kernel() {
    int i = blockIdx.x * blockDim.x + threadIdx.x;
    if (i >= N_NODES) return;
    const int b = min(g_deg[i], N_BUCKET - 1);
    const int r = g_bstart[b] + atomicAdd(&g_bcur[b], 1);
    const int gid = (r % NBLK_G) * 32 + (r / NBLK_G);
    g_perm[gid] = i;
}

__global__ void fill_csr_kernel() {
    int e = blockIdx.x * blockDim.x + threadIdx.x;
    if (e >= N_EDGES) return;
    const int s = g_src[e];
    const int d = g_dst[e];
    const int pos = g_rowptr[d] + atomicAdd(&g_cursor[d], 1);
    g_csri[pos] = s;
}

// ---------------------------------------------------------------------------
// Propagation on z = half2(dinv .* out), 8 threads/node, rank-interleaved
// balanced node assignment (g_perm). Same arithmetic as R9.
// ---------------------------------------------------------------------------
__global__ __launch_bounds__(256) void gather_z_kernel(
    const __half2* __restrict__ z, __half2* __restrict__ nxt,
    float* __restrict__ outf, int last)
{
    const int gid = blockIdx.x * 32 + (threadIdx.x >> 3);
    const int lane = threadIdx.x & 7;
    if (gid >= N_NODES) return;
    const int node = __ldg(&g_perm[gid]);

    const int begin = __ldg(&g_rowptr[node]);
    const int end   = __ldg(&g_rowptr[node + 1]);

    float2 s0 = make_float2(0.f, 0.f);
    float2 s1 = make_float2(0.f, 0.f);
    float2 s2 = make_float2(0.f, 0.f);

    int e = begin;
    for (; e + 2 <= end; e += 2) {
        const int srcA = __ldg(&g_csri[e]);
        const int srcB = __ldg(&g_csri[e + 1]);
        const __half2* pA = z + (size_t)srcA * (D_OUT / 2) + lane;
        const __half2* pB = z + (size_t)srcB * (D_OUT / 2) + lane;
        const float2 a0 = __half22float2(__ldg(pA));
        const float2 a1 = __half22float2(__ldg(pA + 8));
        const float2 a2 = __half22float2(__ldg(pA + 16));
        const float2 b0 = __half22float2(__ldg(pB));
        const float2 b1 = __half22float2(__ldg(pB + 8));
        const float2 b2 = __half22float2(__ldg(pB + 16));
        s0.x += a0.x + b0.x; s0.y += a0.y + b0.y;
        s1.x += a1.x + b1.x; s1.y += a1.y + b1.y;
        s2.x += a2.x + b2.x; s2.y += a2.y + b2.y;
    }
    if (e < end) {
        const int src = __ldg(&g_csri[e]);
        const __half2* p = z + (size_t)src * (D_OUT / 2) + lane;
        const float2 v0 = __half22float2(__ldg(p));
        const float2 v1 = __half22float2(__ldg(p + 8));
        const float2 v2 = __half22float2(__ldg(p + 16));
        s0.x += v0.x; s0.y += v0.y;
        s1.x += v1.x; s1.y += v1.y;
        s2.x += v2.x; s2.y += v2.y;
    }

    {   // self-loop contribution
        const __half2* p = z + (size_t)node * (D_OUT / 2) + lane;
        const float2 v0 = __half22float2(p[0]);
        const float2 v1 = __half22float2(p[8]);
        const float2 v2 = __half22float2(p[16]);
        s0.x += v0.x; s0.y += v0.y;
        s1.x += v1.x; s1.y += v1.y;
        s2.x += v2.x; s2.y += v2.y;
    }

    const float di = __ldg(&g_dinv[node]);
    const float* ph = g_h + (size_t)node * D_OUT + 2 * lane;
    const float2 h0 = *(const float2*)(ph);
    const float2 h1 = *(const float2*)(ph + 16);
    const float2 h2 = *(const float2*)(ph + 32);

    const float w = (1.0f - ALPHA) * di;
    float2 o0 = make_float2(w * s0.x + ALPHA * h0.x, w * s0.y + ALPHA * h0.y);
    float2 o1 = make_float2(w * s1.x + ALPHA * h1.x, w * s1.y + ALPHA * h1.y);
    float2 o2 = make_float2(w * s2.x + ALPHA * h2.x, w * s2.y + ALPHA * h2.y);

    if (last) {
        float* po = outf + (size_t)node * D_OUT + 2 * lane;
        *(float2*)(po)      = o0;
        *(float2*)(po + 16) = o1;
        *(float2*)(po + 32) = o2;
    } else {
        __half2* po = nxt + (size_t)node * (D_OUT / 2) + lane;
        po[0]  = __float22half2_rn(make_float2(di * o0.x, di * o0.y));
        po[8]  = __float22half2_rn(make_float2(di * o1.x, di * o1.y));
        po[16] = __float22half2_rn(make_float2(di * o2.x, di * o2.y));
    }
}

// ---------------------------------------------------------------------------
// Launch. Inputs matched by element count. gemm1 stays at launch slot 3.
// ---------------------------------------------------------------------------
extern "C" void kernel_launch(void* const* d_in, const int* in_sizes, int n_in,
                              void* d_out, int out_size)
{
    const void* x = nullptr; const void* ei = nullptr;
    const void* W1 = nullptr; const void* b1 = nullptr;
    const void* W2 = nullptr; const void* b2 = nullptr;

    for (int i = 0; i < n_in; i++) {
        switch (in_sizes[i]) {
            case 25600000: x  = d_in[i]; break;
            case  3200000: ei = d_in[i]; break;
            case   131072: W1 = d_in[i]; break;
            case      512: b1 = d_in[i]; break;
            case    24576: W2 = d_in[i]; break;
            case       48: b2 = d_in[i]; break;
            default: break;
        }
    }
    if (!x)  x  = d_in[0];
    if (!ei) ei = d_in[1];
    if (!W1) W1 = d_in[2];
    if (!b1) b1 = d_in[3];
    if (!W2) W2 = d_in[4];
    if (!b2) b2 = d_in[5];

    float* out = (float*)d_out;
    const int M = N_NODES;

    __half2* zA;  cudaGetSymbolAddress((void**)&zA, g_zA);
    __half2* zB;  cudaGetSymbolAddress((void**)&zB, g_zB);

    static int smem_set = 0;
    if (!smem_set) {
        cudaFuncSetAttribute(gemm1_tc_kernel,
                             cudaFuncAttributeMaxDynamicSharedMemorySize, G1_SMEM);
        smem_set = 1;
    }

    // 0-2: preprocessing that gemm1 doesn't need (+W1 tf32 pre-round)
    convert_idx_kernel<<<(N_EDGES + 255) / 256, 256>>>(ei);
    prep_kernel<<<(W1_ELEMS + 255) / 256, 256>>>((const float*)W1);
    deg_acc_kernel<<<(N_EDGES + 255) / 256, 256>>>();

    // 3: GEMM1 (target of the ncu capture at launch index 3)
    {
        dim3 grid(D_HID / 128, (M + 127) / 128);
        gemm1_tc_kernel<<<grid, 256, G1_SMEM>>>((const float*)x,
                                                (const float*)b1, M);
    }

    // 4-6: full-chip scan -> rowptr (+dinv folded into pass A)
    blocksum_dinv_kernel<<<NBLK_NODES, 256>>>();
    scan_bsums_kernel<<<1, 512>>>();
    rowptr_kernel<<<NBLK_NODES, 256>>>();

    // 7-9: rank-interleaved degree balancing -> g_perm
    hist_kernel<<<NBLK_NODES, 256>>>();
    bucket_scan_kernel<<<1, 32>>>();
    perm_scatter_kernel<<<NBLK_NODES, 256>>>();

    // 10: CSR fill (src only)
    fill_csr_kernel<<<(N_EDGES + 255) / 256, 256>>>();

    // 11: GEMM2 (writes g_h = h fp32 and zA = half2(dinv*h))
    {
        dim3 grid((M + 127) / 128);
        gemm2_tc_kernel<<<grid, 256>>>((const float*)W2, (const float*)b2, zA, M);
    }

    // 12..21: 10 propagation steps on fp16 z; last step emits fp32 out.
    __half2* cur = zA;
    __half2* nxt = zB;
    for (int s = 0; s < K_STEPS; s++) {
        gather_z_kernel<<<NBLK_G, 256>>>(cur, nxt, out, s == K_STEPS - 1 ? 1 : 0);
        __half2* tmp = cur; cur = nxt; nxt = tmp;
    }
}

// round 13
// speedup vs baseline: 1.1092x; 1.1092x over previous
#include <cuda_runtime.h>
#include <cuda_fp16.h>
#include <cstdint>

// ---------------------------------------------------------------------------
// Problem constants (fixed by the dataset)
// ---------------------------------------------------------------------------
#define N_NODES 100000
#define N_EDGES 1600000
#define D_IN    256
#define D_HID   512
#define D_OUT   48
#define K_STEPS 10
#define ALPHA   0.1f

#define NBLK_NODES ((N_NODES + 255) / 256)   // 391
#define W1_ELEMS  (D_IN * D_HID)             // 131072

// ---------------------------------------------------------------------------
// Scratch (static __device__ arrays; no allocation allowed)
// ---------------------------------------------------------------------------
__device__ __align__(16) float g_hid[(size_t)N_NODES * D_HID];   // tf32-rounded
__device__ __align__(16) float g_h[(size_t)N_NODES * D_OUT];
__device__ __align__(16) float g_w1r[W1_ELEMS];                  // tf32-rounded W1
__device__ __align__(16) __half2 g_zA[(size_t)N_NODES * (D_OUT / 2)];
__device__ __align__(16) __half2 g_zB[(size_t)N_NODES * (D_OUT / 2)];
__device__ float g_dinv[N_NODES];
__device__ int   g_deg[N_NODES];
__device__ int   g_cursor[N_NODES];
__device__ int   g_rowptr[N_NODES + 1];
__device__ int   g_bsum[NBLK_NODES];
__device__ int   g_bpre[NBLK_NODES];
__device__ int   g_src[N_EDGES];
__device__ int   g_dst[N_EDGES];
__device__ int   g_csri[N_EDGES];     // CSR: src index only (norm folded into z)

// ---------------------------------------------------------------------------
// mma helpers
// ---------------------------------------------------------------------------
__device__ __forceinline__ uint32_t f2tf32(float f) {
    uint32_t u;
    asm("cvt.rna.tf32.f32 %0, %1;" : "=r"(u) : "f"(f));
    return u;
}

__device__ __forceinline__ void mma_tf32(float* c,
                                         uint32_t a0, uint32_t a1,
                                         uint32_t a2, uint32_t a3,
                                         uint32_t b0, uint32_t b1) {
    asm volatile(
        "mma.sync.aligned.m16n8k8.row.col.f32.tf32.tf32.f32 "
        "{%0,%1,%2,%3}, {%4,%5,%6,%7}, {%8,%9}, {%0,%1,%2,%3};"
        : "+f"(c[0]), "+f"(c[1]), "+f"(c[2]), "+f"(c[3])
        : "r"(a0), "r"(a1), "r"(a2), "r"(a3), "r"(b0), "r"(b1));
}

#define CP_ASYNC_16(dst_u32, src_ptr) \
    asm volatile("cp.async.cg.shared.global [%0], [%1], 16;" \
                 :: "r"(dst_u32), "l"(src_ptr))
#define CP_COMMIT() asm volatile("cp.async.commit_group;")
#define CP_WAIT(N)  asm volatile("cp.async.wait_group %0;" :: "n"(N))

// ---------------------------------------------------------------------------
// GEMM1: g_hid = relu(x @ W1 + b1), tf32 tensor cores. (R9 version)
// ---------------------------------------------------------------------------
#define AS_STRIDE 20
#define BS_STRIDE 136
#define AS_STAGE (128 * AS_STRIDE)
#define BS_STAGE (16 * BS_STRIDE)
#define G1_SMEM ((3 * AS_STAGE + 3 * BS_STAGE) * 4)   // 56832 bytes
#define N_CHUNK (D_IN / 16)                 // 16

__global__ __launch_bounds__(256, 2) void gemm1_tc_kernel(
    const float* __restrict__ A,    // [M, 256]
    const float* __restrict__ bias, // [512]
    int M)
{
    extern __shared__ float smem[];
    float* AsB = smem;
    float* BsB = smem + 3 * AS_STAGE;

    const int tid = threadIdx.x;
    const int bn = blockIdx.x * 128;
    const int bm = blockIdx.y * 128;

    const int wid = tid >> 5;
    const int lane = tid & 31;
    const int g = lane >> 2;
    const int t = lane & 3;
    const int wm = wid & 1;
    const int wn = wid >> 1;

    float acc[4][4][4];
#pragma unroll
    for (int i = 0; i < 4; i++)
#pragma unroll
        for (int j = 0; j < 4; j++)
#pragma unroll
            for (int q = 0; q < 4; q++) acc[i][j][q] = 0.0f;

    uint32_t aDst[2], bDst[2];
    const float* aSrc[2];
    const float* bSrc[2];
    {
        const uint32_t asBase = (uint32_t)__cvta_generic_to_shared(AsB);
        const uint32_t bsBase = (uint32_t)__cvta_generic_to_shared(BsB);
#pragma unroll
        for (int q = 0; q < 2; q++) {
            const int idx = tid + 256 * q;
            const int ar = idx >> 2;
            const int ac = (idx & 3) * 4;
            aDst[q] = asBase + (ar * AS_STRIDE + ac) * 4;
            const int gr = min(bm + ar, M - 1);
            aSrc[q] = A + (size_t)gr * D_IN + ac;
            const int br = idx >> 5;
            const int bc = (idx & 31) * 4;
            bDst[q] = bsBase + (br * BS_STRIDE + bc) * 4;
            bSrc[q] = g_w1r + (size_t)br * D_HID + bn + bc;
        }
    }

#pragma unroll
    for (int q = 0; q < 2; q++) {
        CP_ASYNC_16(aDst[q], aSrc[q]);
        CP_ASYNC_16(bDst[q], bSrc[q]);
    }
    CP_COMMIT();
#pragma unroll
    for (int q = 0; q < 2; q++) {
        CP_ASYNC_16(aDst[q] + AS_STAGE * 4, aSrc[q] + 16);
        CP_ASYNC_16(bDst[q] + BS_STAGE * 4, bSrc[q] + (size_t)16 * D_HID);
    }
    CP_COMMIT();

    int stC = 0;
    for (int ch = 0; ch < N_CHUNK; ch++) {
        if (ch < N_CHUNK - 1) { CP_WAIT(1); } else { CP_WAIT(0); }
        __syncthreads();

        const float* As = AsB + stC * AS_STAGE;
        const float* Bs = BsB + stC * BS_STAGE;
#pragma unroll
        for (int ks = 0; ks < 2; ks++) {
            const int kb = ks * 8;
            uint32_t af[4][4], bf[4][2];
#pragma unroll
            for (int i = 0; i < 4; i++) {
                const int m = wm * 64 + i * 16 + g;
                af[i][0] = f2tf32(As[m * AS_STRIDE + kb + t]);
                af[i][1] = f2tf32(As[(m + 8) * AS_STRIDE + kb + t]);
                af[i][2] = f2tf32(As[m * AS_STRIDE + kb + t + 4]);
                af[i][3] = f2tf32(As[(m + 8) * AS_STRIDE + kb + t + 4]);
            }
#pragma unroll
            for (int j = 0; j < 4; j++) {
                const int n = wn * 32 + j * 8 + g;
                bf[j][0] = __float_as_uint(Bs[(kb + t) * BS_STRIDE + n]);
                bf[j][1] = __float_as_uint(Bs[(kb + t + 4) * BS_STRIDE + n]);
            }
#pragma unroll
            for (int i = 0; i < 4; i++)
#pragma unroll
                for (int j = 0; j < 4; j++)
                    mma_tf32(acc[i][j], af[i][0], af[i][1], af[i][2], af[i][3],
                             bf[j][0], bf[j][1]);
        }

        if (ch + 2 < N_CHUNK) {
            const int stP = (stC + 2 >= 3) ? stC - 1 : stC + 2;
            const int ko = (ch + 2) * 16;
#pragma unroll
            for (int q = 0; q < 2; q++) {
                CP_ASYNC_16(aDst[q] + stP * AS_STAGE * 4, aSrc[q] + ko);
                CP_ASYNC_16(bDst[q] + stP * BS_STAGE * 4, bSrc[q] + (size_t)ko * D_HID);
            }
            CP_COMMIT();
        }
        stC = (stC + 1 == 3) ? 0 : stC + 1;
    }

    // epilogue: bias + relu + round to tf32 (GEMM2 consumes without converting)
#pragma unroll
    for (int i = 0; i < 4; i++) {
        const int r0 = bm + wm * 64 + i * 16 + g;
        const int r1 = r0 + 8;
#pragma unroll
        for (int j = 0; j < 4; j++) {
            const int gc = bn + wn * 32 + j * 8 + 2 * t;
            const float bz0 = __ldg(bias + gc);
            const float bz1 = __ldg(bias + gc + 1);
            if (r0 < M) {
                float2 v;
                v.x = __uint_as_float(f2tf32(fmaxf(acc[i][j][0] + bz0, 0.f)));
                v.y = __uint_as_float(f2tf32(fmaxf(acc[i][j][1] + bz1, 0.f)));
                *(float2*)(g_hid + (size_t)r0 * D_HID + gc) = v;
            }
            if (r1 < M) {
                float2 v;
                v.x = __uint_as_float(f2tf32(fmaxf(acc[i][j][2] + bz0, 0.f)));
                v.y = __uint_as_float(f2tf32(fmaxf(acc[i][j][3] + bz1, 0.f)));
                *(float2*)(g_hid + (size_t)r1 * D_HID + gc) = v;
            }
        }
    }
}

// ---------------------------------------------------------------------------
// GEMM2 (R9 version): h = g_hid @ W2 + b2 (tf32; g_hid already tf32 bits).
// Epilogue: g_h = h (fp32); zbuf = half2(dinv * h).
// ---------------------------------------------------------------------------
#define G1_STRIDE 136
#define G2_BSTRIDE 56

__global__ __launch_bounds__(256) void gemm2_tc_kernel(
    const float* __restrict__ W2,   // [512, 48]
    const float* __restrict__ bias, // [48]
    __half2* __restrict__ zbuf,     // [M, 24]
    int M)
{
    __shared__ __align__(16) uint32_t As2[32][G1_STRIDE];
    __shared__ __align__(16) uint32_t Bs2[32][G2_BSTRIDE];

    const int tid = threadIdx.x;
    const int bm = blockIdx.x * 128;

    const int wid = tid >> 5;
    const int lane = tid & 31;
    const int g = lane >> 2;
    const int t = lane & 3;
    const int wm = wid & 3;
    const int wn = wid >> 2;

    const int aRow = tid >> 1;
    const int aColBase = (tid & 1) * 16;

    float acc[2][3][4];
#pragma unroll
    for (int i = 0; i < 2; i++)
#pragma unroll
        for (int j = 0; j < 3; j++)
#pragma unroll
            for (int q = 0; q < 4; q++) acc[i][j][q] = 0.0f;

    const int gr = bm + aRow;
    float4 aPre[4];
    float2 bPre[3];

#pragma unroll
    for (int j = 0; j < 4; j++)
        aPre[j] = (gr < M) ? *(const float4*)(g_hid + (size_t)gr * D_HID + aColBase + 4 * j)
                           : make_float4(0.f, 0.f, 0.f, 0.f);
#pragma unroll
    for (int j = 0; j < 3; j++) {
        const int idx = tid + 256 * j;
        const int r = idx / 24;
        const int c = (idx % 24) * 2;
        bPre[j] = *(const float2*)(W2 + (size_t)r * D_OUT + c);
    }

    for (int k0 = 0; k0 < D_HID; k0 += 32) {
#pragma unroll
        for (int j = 0; j < 4; j++) {
            const int c = aColBase + 4 * j;
            As2[c + 0][aRow] = __float_as_uint(aPre[j].x);
            As2[c + 1][aRow] = __float_as_uint(aPre[j].y);
            As2[c + 2][aRow] = __float_as_uint(aPre[j].z);
            As2[c + 3][aRow] = __float_as_uint(aPre[j].w);
        }
#pragma unroll
        for (int j = 0; j < 3; j++) {
            const int idx = tid + 256 * j;
            const int r = idx / 24;
            const int c = (idx % 24) * 2;
            Bs2[r][c + 0] = f2tf32(bPre[j].x);
            Bs2[r][c + 1] = f2tf32(bPre[j].y);
        }
        __syncthreads();

        if (k0 + 32 < D_HID) {
#pragma unroll
            for (int j = 0; j < 4; j++)
                aPre[j] = (gr < M) ? *(const float4*)(g_hid + (size_t)gr * D_HID + k0 + 32 + aColBase + 4 * j)
                                   : make_float4(0.f, 0.f, 0.f, 0.f);
#pragma unroll
            for (int j = 0; j < 3; j++) {
                const int idx = tid + 256 * j;
                const int r = idx / 24;
                const int c = (idx % 24) * 2;
                bPre[j] = *(const float2*)(W2 + (size_t)(k0 + 32 + r) * D_OUT + c);
            }
        }

#pragma unroll
        for (int ks = 0; ks < 4; ks++) {
            const int kb = ks * 8;
            uint32_t af[2][4], bf[3][2];
#pragma unroll
            for (int i = 0; i < 2; i++) {
                const int m = wm * 32 + i * 16 + g;
                af[i][0] = As2[kb + t][m];
                af[i][1] = As2[kb + t][m + 8];
                af[i][2] = As2[kb + t + 4][m];
                af[i][3] = As2[kb + t + 4][m + 8];
            }
#pragma unroll
            for (int j = 0; j < 3; j++) {
                const int n = wn * 24 + j * 8 + g;
                bf[j][0] = Bs2[kb + t][n];
                bf[j][1] = Bs2[kb + t + 4][n];
            }
#pragma unroll
            for (int i = 0; i < 2; i++)
#pragma unroll
                for (int j = 0; j < 3; j++)
                    mma_tf32(acc[i][j], af[i][0], af[i][1], af[i][2], af[i][3],
                             bf[j][0], bf[j][1]);
        }
        __syncthreads();
    }

#pragma unroll
    for (int i = 0; i < 2; i++) {
        const int r0 = bm + wm * 32 + i * 16 + g;
        const int r1 = r0 + 8;
        const float dv0 = (r0 < M) ? __ldg(g_dinv + r0) : 0.f;
        const float dv1 = (r1 < M) ? __ldg(g_dinv + r1) : 0.f;
#pragma unroll
        for (int j = 0; j < 3; j++) {
            const int gc = wn * 24 + j * 8 + 2 * t;
            const float bz0 = __ldg(bias + gc);
            const float bz1 = __ldg(bias + gc + 1);
            if (r0 < M) {
                float2 v = make_float2(acc[i][j][0] + bz0, acc[i][j][1] + bz1);
                *(float2*)(g_h + (size_t)r0 * D_OUT + gc) = v;
                zbuf[(size_t)r0 * (D_OUT / 2) + gc / 2] =
                    __float22half2_rn(make_float2(dv0 * v.x, dv0 * v.y));
            }
            if (r1 < M) {
                float2 v = make_float2(acc[i][j][2] + bz0, acc[i][j][3] + bz1);
                *(float2*)(g_h + (size_t)r1 * D_OUT + gc) = v;
                zbuf[(size_t)r1 * (D_OUT / 2) + gc / 2] =
                    __float22half2_rn(make_float2(dv1 * v.x, dv1 * v.y));
            }
        }
    }
}

// ---------------------------------------------------------------------------
// Graph preprocessing (R9 version)
// ---------------------------------------------------------------------------
__global__ void convert_idx_kernel(const void* __restrict__ ei_raw) {
    const int* p32 = (const int*)ei_raw;
    bool is64 = true;
#pragma unroll
    for (int i = 0; i < 8; i++) is64 = is64 && (p32[2 * i + 1] == 0);

    int e = blockIdx.x * blockDim.x + threadIdx.x;
    if (e >= N_EDGES) return;
    int s, d;
    if (is64) {
        const long long* p64 = (const long long*)ei_raw;
        s = (int)p64[e];
        d = (int)p64[(size_t)N_EDGES + e];
    } else {
        s = p32[e];
        d = p32[(size_t)N_EDGES + e];
    }
    s = min(max(s, 0), N_NODES - 1);
    d = min(max(d, 0), N_NODES - 1);
    g_src[e] = s;
    g_dst[e] = d;
}

__global__ void prep_kernel(const float* __restrict__ W1) {
    int i = blockIdx.x * blockDim.x + threadIdx.x;
    if (i < N_NODES) { g_deg[i] = 0; g_cursor[i] = 0; }
    if (i < W1_ELEMS) g_w1r[i] = __uint_as_float(f2tf32(W1[i]));
}

__global__ void deg_acc_kernel() {
    int e = blockIdx.x * blockDim.x + threadIdx.x;
    if (e < N_EDGES) atomicAdd(&g_deg[g_dst[e]], 1);
}

__global__ __launch_bounds__(256) void blocksum_dinv_kernel() {
    __shared__ int swarp[8];
    const int t = threadIdx.x;
    const int i = blockIdx.x * 256 + t;
    int d = 0;
    if (i < N_NODES) {
        d = g_deg[i];
        g_dinv[i] = rsqrtf((float)(d + 1));   // +1 self-loop
    }
    int v = d;
#pragma unroll
    for (int o = 16; o > 0; o >>= 1) v += __shfl_down_sync(0xffffffffu, v, o);
    if ((t & 31) == 0) swarp[t >> 5] = v;
    __syncthreads();
    if (t == 0) {
        int s = 0;
#pragma unroll
        for (int w = 0; w < 8; w++) s += swarp[w];
        g_bsum[blockIdx.x] = s;
    }
}

__global__ __launch_bounds__(512) void scan_bsums_kernel() {
    __shared__ int sh[512];
    const int t = threadIdx.x;
    sh[t] = (t < NBLK_NODES) ? g_bsum[t] : 0;
    __syncthreads();
#pragma unroll
    for (int off = 1; off < 512; off <<= 1) {
        int v = (t >= off) ? sh[t - off] : 0;
        __syncthreads();
        sh[t] += v;
        __syncthreads();
    }
    if (t < NBLK_NODES) g_bpre[t] = (t == 0) ? 0 : sh[t - 1];
}

__global__ __launch_bounds__(256) void rowptr_kernel() {
    __shared__ int swarp[8];
    const int t = threadIdx.x;
    const int i = blockIdx.x * 256 + t;
    const int lane = t & 31;
    const int w = t >> 5;

    int d = (i < N_NODES) ? g_deg[i] : 0;
    int v = d;
#pragma unroll
    for (int o = 1; o < 32; o <<= 1) {
        int n = __shfl_up_sync(0xffffffffu, v, o);
        if (lane >= o) v += n;
    }
    if (lane == 31) swarp[w] = v;
    __syncthreads();
    if (t == 0) {
        int r = 0;
#pragma unroll
        for (int k = 0; k < 8; k++) { int tmp = swarp[k]; swarp[k] = r; r += tmp; }
    }
    __syncthreads();

    const int excl = g_bpre[blockIdx.x] + swarp[w] + (v - d);
    if (i < N_NODES) {
        g_rowptr[i] = excl;
        if (i == N_NODES - 1) g_rowptr[N_NODES] = excl + d;
    }
}

__global__ void fill_csr_kernel() {
    int e = blockIdx.x * blockDim.x + threadIdx.x;
    if (e >= N_EDGES) return;
    const int s = g_src[e];
    const int d = g_dst[e];
    const int pos = g_rowptr[d] + atomicAdd(&g_cursor[d], 1);
    g_csri[pos] = s;
}

// ---------------------------------------------------------------------------
// Propagation on z = half2(dinv .* out), 8 threads/node, SEQUENTIAL node
// order (locality), 4-unrolled edge loop for MLP (12-16 loads in flight).
// ---------------------------------------------------------------------------
__global__ __launch_bounds__(256) void gather_z_kernel(
    const __half2* __restrict__ z, __half2* __restrict__ nxt,
    float* __restrict__ outf, int last)
{
    const int node = blockIdx.x * 32 + (threadIdx.x >> 3);
    const int lane = threadIdx.x & 7;
    if (node >= N_NODES) return;

    const int begin = __ldg(&g_rowptr[node]);
    const int end   = __ldg(&g_rowptr[node + 1]);

    float2 s0 = make_float2(0.f, 0.f);
    float2 s1 = make_float2(0.f, 0.f);
    float2 s2 = make_float2(0.f, 0.f);

    int e = begin;
    for (; e + 4 <= end; e += 4) {
        const int srcA = __ldg(&g_csri[e]);
        const int srcB = __ldg(&g_csri[e + 1]);
        const int srcC = __ldg(&g_csri[e + 2]);
        const int srcD = __ldg(&g_csri[e + 3]);
        const __half2* pA = z + (size_t)srcA * (D_OUT / 2) + lane;
        const __half2* pB = z + (size_t)srcB * (D_OUT / 2) + lane;
        const __half2* pC = z + (size_t)srcC * (D_OUT / 2) + lane;
        const __half2* pD = z + (size_t)srcD * (D_OUT / 2) + lane;
        // issue all 12 loads before any accumulation (max MLP)
        const __half2 a0 = __ldg(pA),      b0 = __ldg(pB);
        const __half2 c0 = __ldg(pC),      d0 = __ldg(pD);
        const __half2 a1 = __ldg(pA + 8),  b1 = __ldg(pB + 8);
        const __half2 c1 = __ldg(pC + 8),  d1 = __ldg(pD + 8);
        const __half2 a2 = __ldg(pA + 16), b2 = __ldg(pB + 16);
        const __half2 c2 = __ldg(pC + 16), d2 = __ldg(pD + 16);
        float2 f;
        f = __half22float2(a0); s0.x += f.x; s0.y += f.y;
        f = __half22float2(b0); s0.x += f.x; s0.y += f.y;
        f = __half22float2(c0); s0.x += f.x; s0.y += f.y;
        f = __half22float2(d0); s0.x += f.x; s0.y += f.y;
        f = __half22float2(a1); s1.x += f.x; s1.y += f.y;
        f = __half22float2(b1); s1.x += f.x; s1.y += f.y;
        f = __half22float2(c1); s1.x += f.x; s1.y += f.y;
        f = __half22float2(d1); s1.x += f.x; s1.y += f.y;
        f = __half22float2(a2); s2.x += f.x; s2.y += f.y;
        f = __half22float2(b2); s2.x += f.x; s2.y += f.y;
        f = __half22float2(c2); s2.x += f.x; s2.y += f.y;
        f = __half22float2(d2); s2.x += f.x; s2.y += f.y;
    }
    for (; e < end; e++) {
        const int src = __ldg(&g_csri[e]);
        const __half2* p = z + (size_t)src * (D_OUT / 2) + lane;
        const float2 v0 = __half22float2(__ldg(p));
        const float2 v1 = __half22float2(__ldg(p + 8));
        const float2 v2 = __half22float2(__ldg(p + 16));
        s0.x += v0.x; s0.y += v0.y;
        s1.x += v1.x; s1.y += v1.y;
        s2.x += v2.x; s2.y += v2.y;
    }

    {   // self-loop contribution
        const __half2* p = z + (size_t)node * (D_OUT / 2) + lane;
        const float2 v0 = __half22float2(p[0]);
        const float2 v1 = __half22float2(p[8]);
        const float2 v2 = __half22float2(p[16]);
        s0.x += v0.x; s0.y += v0.y;
        s1.x += v1.x; s1.y += v1.y;
        s2.x += v2.x; s2.y += v2.y;
    }

    const float di = __ldg(&g_dinv[node]);
    const float* ph = g_h + (size_t)node * D_OUT + 2 * lane;
    const float2 h0 = *(const float2*)(ph);
    const float2 h1 = *(const float2*)(ph + 16);
    const float2 h2 = *(const float2*)(ph + 32);

    const float w = (1.0f - ALPHA) * di;
    float2 o0 = make_float2(w * s0.x + ALPHA * h0.x, w * s0.y + ALPHA * h0.y);
    float2 o1 = make_float2(w * s1.x + ALPHA * h1.x, w * s1.y + ALPHA * h1.y);
    float2 o2 = make_float2(w * s2.x + ALPHA * h2.x, w * s2.y + ALPHA * h2.y);

    if (last) {
        float* po = outf + (size_t)node * D_OUT + 2 * lane;
        *(float2*)(po)      = o0;
        *(float2*)(po + 16) = o1;
        *(float2*)(po + 32) = o2;
    } else {
        __half2* po = nxt + (size_t)node * (D_OUT / 2) + lane;
        po[0]  = __float22half2_rn(make_float2(di * o0.x, di * o0.y));
        po[8]  = __float22half2_rn(make_float2(di * o1.x, di * o1.y));
        po[16] = __float22half2_rn(make_float2(di * o2.x, di * o2.y));
    }
}

// ---------------------------------------------------------------------------
// Launch. Inputs matched by element count. gemm1 stays at launch slot 3.
// ---------------------------------------------------------------------------
extern "C" void kernel_launch(void* const* d_in, const int* in_sizes, int n_in,
                              void* d_out, int out_size)
{
    const void* x = nullptr; const void* ei = nullptr;
    const void* W1 = nullptr; const void* b1 = nullptr;
    const void* W2 = nullptr; const void* b2 = nullptr;

    for (int i = 0; i < n_in; i++) {
        switch (in_sizes[i]) {
            case 25600000: x  = d_in[i]; break;
            case  3200000: ei = d_in[i]; break;
            case   131072: W1 = d_in[i]; break;
            case      512: b1 = d_in[i]; break;
            case    24576: W2 = d_in[i]; break;
            case       48: b2 = d_in[i]; break;
            default: break;
        }
    }
    if (!x)  x  = d_in[0];
    if (!ei) ei = d_in[1];
    if (!W1) W1 = d_in[2];
    if (!b1) b1 = d_in[3];
    if (!W2) W2 = d_in[4];
    if (!b2) b2 = d_in[5];

    float* out = (float*)d_out;
    const int M = N_NODES;

    __half2* zA;  cudaGetSymbolAddress((void**)&zA, g_zA);
    __half2* zB;  cudaGetSymbolAddress((void**)&zB, g_zB);

    static int smem_set = 0;
    if (!smem_set) {
        cudaFuncSetAttribute(gemm1_tc_kernel,
                             cudaFuncAttributeMaxDynamicSharedMemorySize, G1_SMEM);
        smem_set = 1;
    }

    // 0-2: preprocessing that gemm1 doesn't need (+W1 tf32 pre-round)
    convert_idx_kernel<<<(N_EDGES + 255) / 256, 256>>>(ei);
    prep_kernel<<<(W1_ELEMS + 255) / 256, 256>>>((const float*)W1);
    deg_acc_kernel<<<(N_EDGES + 255) / 256, 256>>>();

    // 3: GEMM1 (target of the ncu capture at launch index 3)
    {
        dim3 grid(D_HID / 128, (M + 127) / 128);
        gemm1_tc_kernel<<<grid, 256, G1_SMEM>>>((const float*)x,
                                                (const float*)b1, M);
    }

    // 4-6: full-chip scan -> rowptr (+dinv folded into pass A)
    blocksum_dinv_kernel<<<NBLK_NODES, 256>>>();
    scan_bsums_kernel<<<1, 512>>>();
    rowptr_kernel<<<NBLK_NODES, 256>>>();

    // 7: CSR fill (src only)
    fill_csr_kernel<<<(N_EDGES + 255) / 256, 256>>>();

    // 8: GEMM2 (writes g_h = h fp32 and zA = half2(dinv*h))
    {
        dim3 grid((M + 127) / 128);
        gemm2_tc_kernel<<<grid, 256>>>((const float*)W2, (const float*)b2, zA, M);
    }

    // 9..18: 10 propagation steps on fp16 z; last step emits fp32 out.
    const int gblocks = (N_NODES + 31) / 32;
    __half2* cur = zA;
    __half2* nxt = zB;
    for (int s = 0; s < K_STEPS; s++) {
        gather_z_kernel<<<gblocks, 256>>>(cur, nxt, out, s == K_STEPS - 1 ? 1 : 0);
        __half2* tmp = cur; cur = nxt; nxt = tmp;
    }
}

// round 14
// speedup vs baseline: 1.1705x; 1.0553x over previous
#include <cuda_runtime.h>
#include <cuda_fp16.h>
#include <cstdint>

// ---------------------------------------------------------------------------
// Problem constants (fixed by the dataset)
// ---------------------------------------------------------------------------
#define N_NODES 100000
#define N_EDGES 1600000
#define D_IN    256
#define D_HID   512
#define D_OUT   48
#define K_STEPS 10
#define ALPHA   0.1f

#define NBLK_NODES ((N_NODES + 255) / 256)   // 391
#define W1_ELEMS  (D_IN * D_HID)             // 131072
#define X_ELEMS   ((size_t)N_NODES * D_IN)   // 25,600,000

// ---------------------------------------------------------------------------
// Scratch (static __device__ arrays; no allocation allowed)
// ---------------------------------------------------------------------------
__device__ __align__(16) float g_hid[(size_t)N_NODES * D_HID];   // tf32-rounded
__device__ __align__(16) float g_h[(size_t)N_NODES * D_OUT];
__device__ __align__(16) __half g_xh[X_ELEMS];                   // fp16 x
__device__ __align__(16) __half g_w1t[W1_ELEMS];                 // W1^T fp16 [512][256]
__device__ __align__(16) __half2 g_zA[(size_t)N_NODES * (D_OUT / 2)];
__device__ __align__(16) __half2 g_zB[(size_t)N_NODES * (D_OUT / 2)];
__device__ float g_dinv[N_NODES];
__device__ int   g_deg[N_NODES];
__device__ int   g_cursor[N_NODES];
__device__ int   g_rowptr[N_NODES + 1];
__device__ int   g_bsum[NBLK_NODES];
__device__ int   g_bpre[NBLK_NODES];
__device__ int   g_src[N_EDGES];
__device__ int   g_dst[N_EDGES];
__device__ int   g_csri[N_EDGES];     // CSR: src index only (norm folded into z)

// ---------------------------------------------------------------------------
// mma helpers
// ---------------------------------------------------------------------------
__device__ __forceinline__ uint32_t f2tf32(float f) {
    uint32_t u;
    asm("cvt.rna.tf32.f32 %0, %1;" : "=r"(u) : "f"(f));
    return u;
}

__device__ __forceinline__ void mma_tf32(float* c,
                                         uint32_t a0, uint32_t a1,
                                         uint32_t a2, uint32_t a3,
                                         uint32_t b0, uint32_t b1) {
    asm volatile(
        "mma.sync.aligned.m16n8k8.row.col.f32.tf32.tf32.f32 "
        "{%0,%1,%2,%3}, {%4,%5,%6,%7}, {%8,%9}, {%0,%1,%2,%3};"
        : "+f"(c[0]), "+f"(c[1]), "+f"(c[2]), "+f"(c[3])
        : "r"(a0), "r"(a1), "r"(a2), "r"(a3), "r"(b0), "r"(b1));
}

__device__ __forceinline__ void mma_f16(float* c,
                                        uint32_t a0, uint32_t a1,
                                        uint32_t a2, uint32_t a3,
                                        uint32_t b0, uint32_t b1) {
    asm volatile(
        "mma.sync.aligned.m16n8k16.row.col.f32.f16.f16.f32 "
        "{%0,%1,%2,%3}, {%4,%5,%6,%7}, {%8,%9}, {%0,%1,%2,%3};"
        : "+f"(c[0]), "+f"(c[1]), "+f"(c[2]), "+f"(c[3])
        : "r"(a0), "r"(a1), "r"(a2), "r"(a3), "r"(b0), "r"(b1));
}

#define CP_ASYNC_16(dst_u32, src_ptr) \
    asm volatile("cp.async.cg.shared.global [%0], [%1], 16;" \
                 :: "r"(dst_u32), "l"(src_ptr))
#define CP_COMMIT() asm volatile("cp.async.commit_group;")
#define CP_WAIT(N)  asm volatile("cp.async.wait_group %0;" :: "n"(N))

// ---------------------------------------------------------------------------
// GEMM1 (fp16): g_hid = tf32(relu(x @ W1 + b1)), fp16 m16n8k16 MMA, fp32 acc.
// 256 threads (8 warps, 2M x 4N), block 128x128, warp tile 64x32, BK=32,
// 3-stage cp.async. A smem [m][k] stride 40 halves; B smem [n][k] stride 40
// (W1 pre-transposed). Banks (20g + t + c) % 32 distinct -> conflict-free.
// fp16 mantissa (10b) == tf32 mantissa -> same accuracy as tf32 path.
// ---------------------------------------------------------------------------
#define A16_STRIDE 40
#define A16_STAGE (128 * A16_STRIDE)        // 5120 halves
#define B16_STAGE (128 * A16_STRIDE)        // 5120 halves
#define G1_SMEM ((3 * A16_STAGE + 3 * B16_STAGE) * 2)   // 61440 bytes
#define N_CHUNK16 (D_IN / 32)               // 8

__global__ __launch_bounds__(256, 2) void gemm1_tc_kernel(
    const float* __restrict__ bias, // [512]
    int M)
{
    extern __shared__ __half smemh[];
    __half* AsB = smemh;
    __half* BsB = smemh + 3 * A16_STAGE;

    const int tid = threadIdx.x;
    const int bn = blockIdx.x * 128;
    const int bm = blockIdx.y * 128;

    const int wid = tid >> 5;
    const int lane = tid & 31;
    const int g = lane >> 2;
    const int t = lane & 3;
    const int wm = wid & 1;      // m offset 0/64
    const int wn = wid >> 1;     // n offset 0/32/64/96

    float acc[4][4][4];
#pragma unroll
    for (int i = 0; i < 4; i++)
#pragma unroll
        for (int j = 0; j < 4; j++)
#pragma unroll
            for (int q = 0; q < 4; q++) acc[i][j][q] = 0.0f;

    // cp.async: A = 128 rows x 64B (4 segs), B same. 512 segs each; 2/thread.
    uint32_t aDst[2], bDst[2];
    const __half* aSrc[2];
    const __half* bSrc[2];
    {
        const uint32_t asBase = (uint32_t)__cvta_generic_to_shared(AsB);
        const uint32_t bsBase = (uint32_t)__cvta_generic_to_shared(BsB);
#pragma unroll
        for (int q = 0; q < 2; q++) {
            const int idx = tid + 256 * q;
            const int row = idx >> 2;             // 0..127
            const int seg = (idx & 3) * 8;        // half offset 0,8,16,24
            aDst[q] = asBase + (row * A16_STRIDE + seg) * 2;
            const int gr = min(bm + row, M - 1);
            aSrc[q] = g_xh + (size_t)gr * D_IN + seg;
            bDst[q] = bsBase + (row * A16_STRIDE + seg) * 2;
            bSrc[q] = g_w1t + (size_t)(bn + row) * D_IN + seg;
        }
    }

    // prologue: stage 0 <- chunk 0, stage 1 <- chunk 1
#pragma unroll
    for (int q = 0; q < 2; q++) {
        CP_ASYNC_16(aDst[q], aSrc[q]);
        CP_ASYNC_16(bDst[q], bSrc[q]);
    }
    CP_COMMIT();
#pragma unroll
    for (int q = 0; q < 2; q++) {
        CP_ASYNC_16(aDst[q] + A16_STAGE * 2, aSrc[q] + 32);
        CP_ASYNC_16(bDst[q] + B16_STAGE * 2, bSrc[q] + 32);
    }
    CP_COMMIT();

    int stC = 0;
    for (int ch = 0; ch < N_CHUNK16; ch++) {
        if (ch < N_CHUNK16 - 1) { CP_WAIT(1); } else { CP_WAIT(0); }
        __syncthreads();

        const __half* As = AsB + stC * A16_STAGE;
        const __half* Bs = BsB + stC * B16_STAGE;
#pragma unroll
        for (int ks = 0; ks < 2; ks++) {
            const int kb = ks * 16;
            uint32_t af[4][4], bf[4][2];
#pragma unroll
            for (int i = 0; i < 4; i++) {
                const int m = wm * 64 + i * 16 + g;
                af[i][0] = *(const uint32_t*)&As[m * A16_STRIDE + kb + 2 * t];
                af[i][1] = *(const uint32_t*)&As[(m + 8) * A16_STRIDE + kb + 2 * t];
                af[i][2] = *(const uint32_t*)&As[m * A16_STRIDE + kb + 2 * t + 8];
                af[i][3] = *(const uint32_t*)&As[(m + 8) * A16_STRIDE + kb + 2 * t + 8];
            }
#pragma unroll
            for (int j = 0; j < 4; j++) {
                const int n = wn * 32 + j * 8 + g;
                bf[j][0] = *(const uint32_t*)&Bs[n * A16_STRIDE + kb + 2 * t];
                bf[j][1] = *(const uint32_t*)&Bs[n * A16_STRIDE + kb + 2 * t + 8];
            }
#pragma unroll
            for (int i = 0; i < 4; i++)
#pragma unroll
                for (int j = 0; j < 4; j++)
                    mma_f16(acc[i][j], af[i][0], af[i][1], af[i][2], af[i][3],
                            bf[j][0], bf[j][1]);
        }

        if (ch + 2 < N_CHUNK16) {
            const int stP = (stC + 2 >= 3) ? stC - 1 : stC + 2;
            const int ko = (ch + 2) * 32;
#pragma unroll
            for (int q = 0; q < 2; q++) {
                CP_ASYNC_16(aDst[q] + stP * A16_STAGE * 2, aSrc[q] + ko);
                CP_ASYNC_16(bDst[q] + stP * B16_STAGE * 2, bSrc[q] + ko);
            }
            CP_COMMIT();
        }
        stC = (stC + 1 == 3) ? 0 : stC + 1;
    }

    // epilogue: bias + relu + round to tf32 (GEMM2 consumes without converting)
#pragma unroll
    for (int i = 0; i < 4; i++) {
        const int r0 = bm + wm * 64 + i * 16 + g;
        const int r1 = r0 + 8;
#pragma unroll
        for (int j = 0; j < 4; j++) {
            const int gc = bn + wn * 32 + j * 8 + 2 * t;
            const float bz0 = __ldg(bias + gc);
            const float bz1 = __ldg(bias + gc + 1);
            if (r0 < M) {
                float2 v;
                v.x = __uint_as_float(f2tf32(fmaxf(acc[i][j][0] + bz0, 0.f)));
                v.y = __uint_as_float(f2tf32(fmaxf(acc[i][j][1] + bz1, 0.f)));
                *(float2*)(g_hid + (size_t)r0 * D_HID + gc) = v;
            }
            if (r1 < M) {
                float2 v;
                v.x = __uint_as_float(f2tf32(fmaxf(acc[i][j][2] + bz0, 0.f)));
                v.y = __uint_as_float(f2tf32(fmaxf(acc[i][j][3] + bz1, 0.f)));
                *(float2*)(g_hid + (size_t)r1 * D_HID + gc) = v;
            }
        }
    }
}

// ---------------------------------------------------------------------------
// GEMM2 (R9 version): h = g_hid @ W2 + b2 (tf32; g_hid already tf32 bits).
// Epilogue: g_h = h (fp32); zbuf = half2(dinv * h).
// ---------------------------------------------------------------------------
#define G1_STRIDE 136
#define G2_BSTRIDE 56

__global__ __launch_bounds__(256) void gemm2_tc_kernel(
    const float* __restrict__ W2,   // [512, 48]
    const float* __restrict__ bias, // [48]
    __half2* __restrict__ zbuf,     // [M, 24]
    int M)
{
    __shared__ __align__(16) uint32_t As2[32][G1_STRIDE];
    __shared__ __align__(16) uint32_t Bs2[32][G2_BSTRIDE];

    const int tid = threadIdx.x;
    const int bm = blockIdx.x * 128;

    const int wid = tid >> 5;
    const int lane = tid & 31;
    const int g = lane >> 2;
    const int t = lane & 3;
    const int wm = wid & 3;
    const int wn = wid >> 2;

    const int aRow = tid >> 1;
    const int aColBase = (tid & 1) * 16;

    float acc[2][3][4];
#pragma unroll
    for (int i = 0; i < 2; i++)
#pragma unroll
        for (int j = 0; j < 3; j++)
#pragma unroll
            for (int q = 0; q < 4; q++) acc[i][j][q] = 0.0f;

    const int gr = bm + aRow;
    float4 aPre[4];
    float2 bPre[3];

#pragma unroll
    for (int j = 0; j < 4; j++)
        aPre[j] = (gr < M) ? *(const float4*)(g_hid + (size_t)gr * D_HID + aColBase + 4 * j)
                           : make_float4(0.f, 0.f, 0.f, 0.f);
#pragma unroll
    for (int j = 0; j < 3; j++) {
        const int idx = tid + 256 * j;
        const int r = idx / 24;
        const int c = (idx % 24) * 2;
        bPre[j] = *(const float2*)(W2 + (size_t)r * D_OUT + c);
    }

    for (int k0 = 0; k0 < D_HID; k0 += 32) {
#pragma unroll
        for (int j = 0; j < 4; j++) {
            const int c = aColBase + 4 * j;
            As2[c + 0][aRow] = __float_as_uint(aPre[j].x);
            As2[c + 1][aRow] = __float_as_uint(aPre[j].y);
            As2[c + 2][aRow] = __float_as_uint(aPre[j].z);
            As2[c + 3][aRow] = __float_as_uint(aPre[j].w);
        }
#pragma unroll
        for (int j = 0; j < 3; j++) {
            const int idx = tid + 256 * j;
            const int r = idx / 24;
            const int c = (idx % 24) * 2;
            Bs2[r][c + 0] = f2tf32(bPre[j].x);
            Bs2[r][c + 1] = f2tf32(bPre[j].y);
        }
        __syncthreads();

        if (k0 + 32 < D_HID) {
#pragma unroll
            for (int j = 0; j < 4; j++)
                aPre[j] = (gr < M) ? *(const float4*)(g_hid + (size_t)gr * D_HID + k0 + 32 + aColBase + 4 * j)
                                   : make_float4(0.f, 0.f, 0.f, 0.f);
#pragma unroll
            for (int j = 0; j < 3; j++) {
                const int idx = tid + 256 * j;
                const int r = idx / 24;
                const int c = (idx % 24) * 2;
                bPre[j] = *(const float2*)(W2 + (size_t)(k0 + 32 + r) * D_OUT + c);
            }
        }

#pragma unroll
        for (int ks = 0; ks < 4; ks++) {
            const int kb = ks * 8;
            uint32_t af[2][4], bf[3][2];
#pragma unroll
            for (int i = 0; i < 2; i++) {
                const int m = wm * 32 + i * 16 + g;
                af[i][0] = As2[kb + t][m];
                af[i][1] = As2[kb + t][m + 8];
                af[i][2] = As2[kb + t + 4][m];
                af[i][3] = As2[kb + t + 4][m + 8];
            }
#pragma unroll
            for (int j = 0; j < 3; j++) {
                const int n = wn * 24 + j * 8 + g;
                bf[j][0] = Bs2[kb + t][n];
                bf[j][1] = Bs2[kb + t + 4][n];
            }
#pragma unroll
            for (int i = 0; i < 2; i++)
#pragma unroll
                for (int j = 0; j < 3; j++)
                    mma_tf32(acc[i][j], af[i][0], af[i][1], af[i][2], af[i][3],
                             bf[j][0], bf[j][1]);
        }
        __syncthreads();
    }

#pragma unroll
    for (int i = 0; i < 2; i++) {
        const int r0 = bm + wm * 32 + i * 16 + g;
        const int r1 = r0 + 8;
        const float dv0 = (r0 < M) ? __ldg(g_dinv + r0) : 0.f;
        const float dv1 = (r1 < M) ? __ldg(g_dinv + r1) : 0.f;
#pragma unroll
        for (int j = 0; j < 3; j++) {
            const int gc = wn * 24 + j * 8 + 2 * t;
            const float bz0 = __ldg(bias + gc);
            const float bz1 = __ldg(bias + gc + 1);
            if (r0 < M) {
                float2 v = make_float2(acc[i][j][0] + bz0, acc[i][j][1] + bz1);
                *(float2*)(g_h + (size_t)r0 * D_OUT + gc) = v;
                zbuf[(size_t)r0 * (D_OUT / 2) + gc / 2] =
                    __float22half2_rn(make_float2(dv0 * v.x, dv0 * v.y));
            }
            if (r1 < M) {
                float2 v = make_float2(acc[i][j][2] + bz0, acc[i][j][3] + bz1);
                *(float2*)(g_h + (size_t)r1 * D_OUT + gc) = v;
                zbuf[(size_t)r1 * (D_OUT / 2) + gc / 2] =
                    __float22half2_rn(make_float2(dv1 * v.x, dv1 * v.y));
            }
        }
    }
}

// ---------------------------------------------------------------------------
// Graph preprocessing
// ---------------------------------------------------------------------------
__global__ void convert_idx_kernel(const void* __restrict__ ei_raw) {
    const int* p32 = (const int*)ei_raw;
    bool is64 = true;
#pragma unroll
    for (int i = 0; i < 8; i++) is64 = is64 && (p32[2 * i + 1] == 0);

    int e = blockIdx.x * blockDim.x + threadIdx.x;
    if (e >= N_EDGES) return;
    int s, d;
    if (is64) {
        const long long* p64 = (const long long*)ei_raw;
        s = (int)p64[e];
        d = (int)p64[(size_t)N_EDGES + e];
    } else {
        s = p32[e];
        d = p32[(size_t)N_EDGES + e];
    }
    s = min(max(s, 0), N_NODES - 1);
    d = min(max(d, 0), N_NODES - 1);
    g_src[e] = s;
    g_dst[e] = d;
}

// Fused: zero deg/cursor + transpose W1 -> fp16 [n][k].
__global__ void prep_kernel(const float* __restrict__ W1) {
    int i = blockIdx.x * blockDim.x + threadIdx.x;
    if (i < N_NODES) { g_deg[i] = 0; g_cursor[i] = 0; }
    if (i < W1_ELEMS) {
        const int k = i / D_HID;
        const int n = i % D_HID;
        g_w1t[(size_t)n * D_IN + k] = __float2half(W1[i]);
    }
}

// Convert x to fp16 (vectorized: 4 floats -> 4 halves per thread).
__global__ void convert_x_kernel(const float* __restrict__ x) {
    const size_t i = (size_t)(blockIdx.x * blockDim.x + threadIdx.x) * 4;
    if (i >= X_ELEMS) return;
    const float4 v = *(const float4*)(x + i);
    __half2 h0 = __float22half2_rn(make_float2(v.x, v.y));
    __half2 h1 = __float22half2_rn(make_float2(v.z, v.w));
    *(uint2*)(g_xh + i) = make_uint2(*(uint32_t*)&h0, *(uint32_t*)&h1);
}

__global__ void deg_acc_kernel() {
    int e = blockIdx.x * blockDim.x + threadIdx.x;
    if (e < N_EDGES) atomicAdd(&g_deg[g_dst[e]], 1);
}

__global__ __launch_bounds__(256) void blocksum_dinv_kernel() {
    __shared__ int swarp[8];
    const int t = threadIdx.x;
    const int i = blockIdx.x * 256 + t;
    int d = 0;
    if (i < N_NODES) {
        d = g_deg[i];
        g_dinv[i] = rsqrtf((float)(d + 1));   // +1 self-loop
    }
    int v = d;
#pragma unroll
    for (int o = 16; o > 0; o >>= 1) v += __shfl_down_sync(0xffffffffu, v, o);
    if ((t & 31) == 0) swarp[t >> 5] = v;
    __syncthreads();
    if (t == 0) {
        int s = 0;
#pragma unroll
        for (int w = 0; w < 8; w++) s += swarp[w];
        g_bsum[blockIdx.x] = s;
    }
}

__global__ __launch_bounds__(512) void scan_bsums_kernel() {
    __shared__ int sh[512];
    const int t = threadIdx.x;
    sh[t] = (t < NBLK_NODES) ? g_bsum[t] : 0;
    __syncthreads();
#pragma unroll
    for (int off = 1; off < 512; off <<= 1) {
        int v = (t >= off) ? sh[t - off] : 0;
        __syncthreads();
        sh[t] += v;
        __syncthreads();
    }
    if (t < NBLK_NODES) g_bpre[t] = (t == 0) ? 0 : sh[t - 1];
}

__global__ __launch_bounds__(256) void rowptr_kernel() {
    __shared__ int swarp[8];
    const int t = threadIdx.x;
    const int i = blockIdx.x * 256 + t;
    const int lane = t & 31;
    const int w = t >> 5;

    int d = (i < N_NODES) ? g_deg[i] : 0;
    int v = d;
#pragma unroll
    for (int o = 1; o < 32; o <<= 1) {
        int n = __shfl_up_sync(0xffffffffu, v, o);
        if (lane >= o) v += n;
    }
    if (lane == 31) swarp[w] = v;
    __syncthreads();
    if (t == 0) {
        int r = 0;
#pragma unroll
        for (int k = 0; k < 8; k++) { int tmp = swarp[k]; swarp[k] = r; r += tmp; }
    }
    __syncthreads();

    const int excl = g_bpre[blockIdx.x] + swarp[w] + (v - d);
    if (i < N_NODES) {
        g_rowptr[i] = excl;
        if (i == N_NODES - 1) g_rowptr[N_NODES] = excl + d;
    }
}

__global__ void fill_csr_kernel() {
    int e = blockIdx.x * blockDim.x + threadIdx.x;
    if (e >= N_EDGES) return;
    const int s = g_src[e];
    const int d = g_dst[e];
    const int pos = g_rowptr[d] + atomicAdd(&g_cursor[d], 1);
    g_csri[pos] = s;
}

// ---------------------------------------------------------------------------
// Propagation (exact R9 version): z = half2(dinv .* out), 8 threads/node,
// sequential node order, 2-unrolled edge loop.
// ---------------------------------------------------------------------------
__global__ __launch_bounds__(256) void gather_z_kernel(
    const __half2* __restrict__ z, __half2* __restrict__ nxt,
    float* __restrict__ outf, int last)
{
    const int node = blockIdx.x * 32 + (threadIdx.x >> 3);
    const int lane = threadIdx.x & 7;
    if (node >= N_NODES) return;

    const int begin = g_rowptr[node];
    const int end   = g_rowptr[node + 1];

    float2 s0 = make_float2(0.f, 0.f);
    float2 s1 = make_float2(0.f, 0.f);
    float2 s2 = make_float2(0.f, 0.f);

    int e = begin;
    for (; e + 2 <= end; e += 2) {
        const int srcA = __ldg(&g_csri[e]);
        const int srcB = __ldg(&g_csri[e + 1]);
        const __half2* pA = z + (size_t)srcA * (D_OUT / 2) + lane;
        const __half2* pB = z + (size_t)srcB * (D_OUT / 2) + lane;
        const float2 a0 = __half22float2(__ldg(pA));
        const float2 a1 = __half22float2(__ldg(pA + 8));
        const float2 a2 = __half22float2(__ldg(pA + 16));
        const float2 b0 = __half22float2(__ldg(pB));
        const float2 b1 = __half22float2(__ldg(pB + 8));
        const float2 b2 = __half22float2(__ldg(pB + 16));
        s0.x += a0.x + b0.x; s0.y += a0.y + b0.y;
        s1.x += a1.x + b1.x; s1.y += a1.y + b1.y;
        s2.x += a2.x + b2.x; s2.y += a2.y + b2.y;
    }
    if (e < end) {
        const int src = __ldg(&g_csri[e]);
        const __half2* p = z + (size_t)src * (D_OUT / 2) + lane;
        const float2 v0 = __half22float2(__ldg(p));
        const float2 v1 = __half22float2(__ldg(p + 8));
        const float2 v2 = __half22float2(__ldg(p + 16));
        s0.x += v0.x; s0.y += v0.y;
        s1.x += v1.x; s1.y += v1.y;
        s2.x += v2.x; s2.y += v2.y;
    }

    {   // self-loop contribution
        const __half2* p = z + (size_t)node * (D_OUT / 2) + lane;
        const float2 v0 = __half22float2(p[0]);
        const float2 v1 = __half22float2(p[8]);
        const float2 v2 = __half22float2(p[16]);
        s0.x += v0.x; s0.y += v0.y;
        s1.x += v1.x; s1.y += v1.y;
        s2.x += v2.x; s2.y += v2.y;
    }

    const float di = g_dinv[node];
    const float* ph = g_h + (size_t)node * D_OUT + 2 * lane;
    const float2 h0 = *(const float2*)(ph);
    const float2 h1 = *(const float2*)(ph + 16);
    const float2 h2 = *(const float2*)(ph + 32);

    const float w = (1.0f - ALPHA) * di;
    float2 o0 = make_float2(w * s0.x + ALPHA * h0.x, w * s0.y + ALPHA * h0.y);
    float2 o1 = make_float2(w * s1.x + ALPHA * h1.x, w * s1.y + ALPHA * h1.y);
    float2 o2 = make_float2(w * s2.x + ALPHA * h2.x, w * s2.y + ALPHA * h2.y);

    if (last) {
        float* po = outf + (size_t)node * D_OUT + 2 * lane;
        *(float2*)(po)      = o0;
        *(float2*)(po + 16) = o1;
        *(float2*)(po + 32) = o2;
    } else {
        __half2* po = nxt + (size_t)node * (D_OUT / 2) + lane;
        po[0]  = __float22half2_rn(make_float2(di * o0.x, di * o0.y));
        po[8]  = __float22half2_rn(make_float2(di * o1.x, di * o1.y));
        po[16] = __float22half2_rn(make_float2(di * o2.x, di * o2.y));
    }
}

// ---------------------------------------------------------------------------
// Launch. Inputs matched by element count. gemm1 stays at launch slot 3.
// ---------------------------------------------------------------------------
extern "C" void kernel_launch(void* const* d_in, const int* in_sizes, int n_in,
                              void* d_out, int out_size)
{
    const void* x = nullptr; const void* ei = nullptr;
    const void* W1 = nullptr; const void* b1 = nullptr;
    const void* W2 = nullptr; const void* b2 = nullptr;

    for (int i = 0; i < n_in; i++) {
        switch (in_sizes[i]) {
            case 25600000: x  = d_in[i]; break;
            case  3200000: ei = d_in[i]; break;
            case   131072: W1 = d_in[i]; break;
            case      512: b1 = d_in[i]; break;
            case    24576: W2 = d_in[i]; break;
            case       48: b2 = d_in[i]; break;
            default: break;
        }
    }
    if (!x)  x  = d_in[0];
    if (!ei) ei = d_in[1];
    if (!W1) W1 = d_in[2];
    if (!b1) b1 = d_in[3];
    if (!W2) W2 = d_in[4];
    if (!b2) b2 = d_in[5];

    float* out = (float*)d_out;
    const int M = N_NODES;

    __half2* zA;  cudaGetSymbolAddress((void**)&zA, g_zA);
    __half2* zB;  cudaGetSymbolAddress((void**)&zB, g_zB);

    static int smem_set = 0;
    if (!smem_set) {
        cudaFuncSetAttribute(gemm1_tc_kernel,
                             cudaFuncAttributeMaxDynamicSharedMemorySize, G1_SMEM);
        smem_set = 1;
    }

    // 0-2: preprocessing gemm1 needs (x/W1 fp16) + index convert
    convert_idx_kernel<<<(N_EDGES + 255) / 256, 256>>>(ei);
    prep_kernel<<<(W1_ELEMS + 255) / 256, 256>>>((const float*)W1);
    convert_x_kernel<<<(int)((X_ELEMS / 4 + 255) / 256), 256>>>((const float*)x);

    // 3: GEMM1 fp16 (target of the ncu capture at launch index 3)
    {
        dim3 grid(D_HID / 128, (M + 127) / 128);
        gemm1_tc_kernel<<<grid, 256, G1_SMEM>>>((const float*)b1, M);
    }

    // 4-7: degree accumulate + full-chip scan -> rowptr (+dinv in pass A)
    deg_acc_kernel<<<(N_EDGES + 255) / 256, 256>>>();
    blocksum_dinv_kernel<<<NBLK_NODES, 256>>>();
    scan_bsums_kernel<<<1, 512>>>();
    rowptr_kernel<<<NBLK_NODES, 256>>>();

    // 8: CSR fill (src only)
    fill_csr_kernel<<<(N_EDGES + 255) / 256, 256>>>();

    // 9: GEMM2 (writes g_h = h fp32 and zA = half2(dinv*h))
    {
        dim3 grid((M + 127) / 128);
        gemm2_tc_kernel<<<grid, 256>>>((const float*)W2, (const float*)b2, zA, M);
    }

    // 10..19: 10 propagation steps on fp16 z; last step emits fp32 out.
    const int gblocks = (N_NODES + 31) / 32;
    __half2* cur = zA;
    __half2* nxt = zB;
    for (int s = 0; s < K_STEPS; s++) {
        gather_z_kernel<<<gblocks, 256>>>(cur, nxt, out, s == K_STEPS - 1 ? 1 : 0);
        __half2* tmp = cur; cur = nxt; nxt = tmp;
    }
}

// round 15
// speedup vs baseline: 1.2587x; 1.0754x over previous
#include <cuda_runtime.h>
#include <cuda_fp16.h>
#include <cstdint>

// ---------------------------------------------------------------------------
// Problem constants (fixed by the dataset)
// ---------------------------------------------------------------------------
#define N_NODES 100000
#define N_EDGES 1600000
#define D_IN    256
#define D_HID   512
#define D_OUT   48
#define K_STEPS 10
#define ALPHA   0.1f

#define NBLK_NODES ((N_NODES + 255) / 256)   // 391
#define W1_ELEMS  (D_IN * D_HID)             // 131072
#define W2_ELEMS  (D_HID * D_OUT)            // 24576
#define X_ELEMS   ((size_t)N_NODES * D_IN)   // 25,600,000

// ---------------------------------------------------------------------------
// Scratch (static __device__ arrays; no allocation allowed)
// ---------------------------------------------------------------------------
__device__ __align__(16) __half g_hidh[(size_t)N_NODES * D_HID];  // fp16 hid
__device__ __align__(16) float g_h[(size_t)N_NODES * D_OUT];
__device__ __align__(16) __half g_xh[X_ELEMS];                    // fp16 x
__device__ __align__(16) __half g_w1t[W1_ELEMS];                  // W1^T fp16 [512][256]
__device__ __align__(16) __half g_w2t[W2_ELEMS];                  // W2^T fp16 [48][512]
__device__ __align__(16) __half2 g_zA[(size_t)N_NODES * (D_OUT / 2)];
__device__ __align__(16) __half2 g_zB[(size_t)N_NODES * (D_OUT / 2)];
__device__ float g_dinv[N_NODES];
__device__ int   g_deg[N_NODES];
__device__ int   g_cursor[N_NODES];
__device__ int   g_rowptr[N_NODES + 1];
__device__ int   g_bsum[NBLK_NODES];
__device__ int   g_bpre[NBLK_NODES];
__device__ int   g_src[N_EDGES];
__device__ int   g_dst[N_EDGES];
__device__ int   g_csri[N_EDGES];     // CSR: src index only (norm folded into z)

// ---------------------------------------------------------------------------
// mma helper
// ---------------------------------------------------------------------------
__device__ __forceinline__ void mma_f16(float* c,
                                        uint32_t a0, uint32_t a1,
                                        uint32_t a2, uint32_t a3,
                                        uint32_t b0, uint32_t b1) {
    asm volatile(
        "mma.sync.aligned.m16n8k16.row.col.f32.f16.f16.f32 "
        "{%0,%1,%2,%3}, {%4,%5,%6,%7}, {%8,%9}, {%0,%1,%2,%3};"
        : "+f"(c[0]), "+f"(c[1]), "+f"(c[2]), "+f"(c[3])
        : "r"(a0), "r"(a1), "r"(a2), "r"(a3), "r"(b0), "r"(b1));
}

#define CP_ASYNC_16(dst_u32, src_ptr) \
    asm volatile("cp.async.cg.shared.global [%0], [%1], 16;" \
                 :: "r"(dst_u32), "l"(src_ptr))
#define CP_COMMIT() asm volatile("cp.async.commit_group;")
#define CP_WAIT(N)  asm volatile("cp.async.wait_group %0;" :: "n"(N))

// ---------------------------------------------------------------------------
// GEMM1 (fp16): g_hidh = half(relu(x @ W1 + b1)), fp16 m16n8k16, fp32 acc.
// (R14 structure; epilogue now stores fp16 -> write traffic halves.)
// ---------------------------------------------------------------------------
#define A16_STRIDE 40
#define A16_STAGE (128 * A16_STRIDE)        // 5120 halves
#define B16_STAGE (128 * A16_STRIDE)
#define G1_SMEM ((3 * A16_STAGE + 3 * B16_STAGE) * 2)   // 61440 bytes
#define N_CHUNK16 (D_IN / 32)               // 8

__global__ __launch_bounds__(256, 2) void gemm1_tc_kernel(
    const float* __restrict__ bias, // [512]
    int M)
{
    extern __shared__ __half smemh[];
    __half* AsB = smemh;
    __half* BsB = smemh + 3 * A16_STAGE;

    const int tid = threadIdx.x;
    const int bn = blockIdx.x * 128;
    const int bm = blockIdx.y * 128;

    const int wid = tid >> 5;
    const int lane = tid & 31;
    const int g = lane >> 2;
    const int t = lane & 3;
    const int wm = wid & 1;
    const int wn = wid >> 1;

    float acc[4][4][4];
#pragma unroll
    for (int i = 0; i < 4; i++)
#pragma unroll
        for (int j = 0; j < 4; j++)
#pragma unroll
            for (int q = 0; q < 4; q++) acc[i][j][q] = 0.0f;

    uint32_t aDst[2], bDst[2];
    const __half* aSrc[2];
    const __half* bSrc[2];
    {
        const uint32_t asBase = (uint32_t)__cvta_generic_to_shared(AsB);
        const uint32_t bsBase = (uint32_t)__cvta_generic_to_shared(BsB);
#pragma unroll
        for (int q = 0; q < 2; q++) {
            const int idx = tid + 256 * q;
            const int row = idx >> 2;
            const int seg = (idx & 3) * 8;
            aDst[q] = asBase + (row * A16_STRIDE + seg) * 2;
            const int gr = min(bm + row, M - 1);
            aSrc[q] = g_xh + (size_t)gr * D_IN + seg;
            bDst[q] = bsBase + (row * A16_STRIDE + seg) * 2;
            bSrc[q] = g_w1t + (size_t)(bn + row) * D_IN + seg;
        }
    }

#pragma unroll
    for (int q = 0; q < 2; q++) {
        CP_ASYNC_16(aDst[q], aSrc[q]);
        CP_ASYNC_16(bDst[q], bSrc[q]);
    }
    CP_COMMIT();
#pragma unroll
    for (int q = 0; q < 2; q++) {
        CP_ASYNC_16(aDst[q] + A16_STAGE * 2, aSrc[q] + 32);
        CP_ASYNC_16(bDst[q] + B16_STAGE * 2, bSrc[q] + 32);
    }
    CP_COMMIT();

    int stC = 0;
    for (int ch = 0; ch < N_CHUNK16; ch++) {
        if (ch < N_CHUNK16 - 1) { CP_WAIT(1); } else { CP_WAIT(0); }
        __syncthreads();

        const __half* As = AsB + stC * A16_STAGE;
        const __half* Bs = BsB + stC * B16_STAGE;
#pragma unroll
        for (int ks = 0; ks < 2; ks++) {
            const int kb = ks * 16;
            uint32_t af[4][4], bf[4][2];
#pragma unroll
            for (int i = 0; i < 4; i++) {
                const int m = wm * 64 + i * 16 + g;
                af[i][0] = *(const uint32_t*)&As[m * A16_STRIDE + kb + 2 * t];
                af[i][1] = *(const uint32_t*)&As[(m + 8) * A16_STRIDE + kb + 2 * t];
                af[i][2] = *(const uint32_t*)&As[m * A16_STRIDE + kb + 2 * t + 8];
                af[i][3] = *(const uint32_t*)&As[(m + 8) * A16_STRIDE + kb + 2 * t + 8];
            }
#pragma unroll
            for (int j = 0; j < 4; j++) {
                const int n = wn * 32 + j * 8 + g;
                bf[j][0] = *(const uint32_t*)&Bs[n * A16_STRIDE + kb + 2 * t];
                bf[j][1] = *(const uint32_t*)&Bs[n * A16_STRIDE + kb + 2 * t + 8];
            }
#pragma unroll
            for (int i = 0; i < 4; i++)
#pragma unroll
                for (int j = 0; j < 4; j++)
                    mma_f16(acc[i][j], af[i][0], af[i][1], af[i][2], af[i][3],
                            bf[j][0], bf[j][1]);
        }

        if (ch + 2 < N_CHUNK16) {
            const int stP = (stC + 2 >= 3) ? stC - 1 : stC + 2;
            const int ko = (ch + 2) * 32;
#pragma unroll
            for (int q = 0; q < 2; q++) {
                CP_ASYNC_16(aDst[q] + stP * A16_STAGE * 2, aSrc[q] + ko);
                CP_ASYNC_16(bDst[q] + stP * B16_STAGE * 2, bSrc[q] + ko);
            }
            CP_COMMIT();
        }
        stC = (stC + 1 == 3) ? 0 : stC + 1;
    }

    // epilogue: bias + relu -> fp16 store (half the write traffic)
#pragma unroll
    for (int i = 0; i < 4; i++) {
        const int r0 = bm + wm * 64 + i * 16 + g;
        const int r1 = r0 + 8;
#pragma unroll
        for (int j = 0; j < 4; j++) {
            const int gc = bn + wn * 32 + j * 8 + 2 * t;
            const float bz0 = __ldg(bias + gc);
            const float bz1 = __ldg(bias + gc + 1);
            if (r0 < M) {
                *(__half2*)(g_hidh + (size_t)r0 * D_HID + gc) =
                    __float22half2_rn(make_float2(fmaxf(acc[i][j][0] + bz0, 0.f),
                                                  fmaxf(acc[i][j][1] + bz1, 0.f)));
            }
            if (r1 < M) {
                *(__half2*)(g_hidh + (size_t)r1 * D_HID + gc) =
                    __float22half2_rn(make_float2(fmaxf(acc[i][j][2] + bz0, 0.f),
                                                  fmaxf(acc[i][j][3] + bz1, 0.f)));
            }
        }
    }
}

// ---------------------------------------------------------------------------
// GEMM2 (fp16): h = hid @ W2 + b2, fp16 m16n8k16, fp32 acc.
// R9 staging discipline: register-prefetch -> smem for BOTH operands.
// A: g_hidh [m][k] -> smem [128][40] halves. B: g_w2t [48][512] (pre-
// transposed in prep) -> smem [48][40]. Fragment banks 20g+t distinct.
// Epilogue: g_h = h (fp32); zbuf = half2(dinv * h).
// ---------------------------------------------------------------------------
#define A2S 40

__global__ __launch_bounds__(256) void gemm2_tc_kernel(
    const float* __restrict__ bias, // [48]
    __half2* __restrict__ zbuf,     // [M, 24]
    int M)
{
    __shared__ __align__(16) __half As2h[128][A2S];
    __shared__ __align__(16) __half Bs2h[48][A2S];

    const int tid = threadIdx.x;
    const int bm = blockIdx.x * 128;

    const int wid = tid >> 5;
    const int lane = tid & 31;
    const int g = lane >> 2;
    const int t = lane & 3;
    const int wm = wid & 3;    // 32 rows each
    const int wn = wid >> 2;   // 24 cols each

    const int aRow = tid >> 1;
    const int aCol = (tid & 1) * 16;     // half offset in 32-half chunk
    const int gr = min(bm + aRow, M - 1);

    const int bn48 = tid >> 2;           // 0..63 (only <48 active)
    const int bseg = (tid & 3) * 8;      // half offset

    float acc[2][3][4];
#pragma unroll
    for (int i = 0; i < 2; i++)
#pragma unroll
        for (int j = 0; j < 3; j++)
#pragma unroll
            for (int q = 0; q < 4; q++) acc[i][j][q] = 0.0f;

    uint4 aPre[2];
    uint4 bPre = make_uint4(0, 0, 0, 0);
    aPre[0] = *(const uint4*)(g_hidh + (size_t)gr * D_HID + aCol);
    aPre[1] = *(const uint4*)(g_hidh + (size_t)gr * D_HID + aCol + 8);
    if (bn48 < 48)
        bPre = *(const uint4*)(g_w2t + (size_t)bn48 * D_HID + bseg);

    for (int k0 = 0; k0 < D_HID; k0 += 32) {
        *(uint4*)&As2h[aRow][aCol]     = aPre[0];
        *(uint4*)&As2h[aRow][aCol + 8] = aPre[1];
        if (bn48 < 48)
            *(uint4*)&Bs2h[bn48][bseg] = bPre;
        __syncthreads();

        if (k0 + 32 < D_HID) {
            aPre[0] = *(const uint4*)(g_hidh + (size_t)gr * D_HID + k0 + 32 + aCol);
            aPre[1] = *(const uint4*)(g_hidh + (size_t)gr * D_HID + k0 + 32 + aCol + 8);
            if (bn48 < 48)
                bPre = *(const uint4*)(g_w2t + (size_t)bn48 * D_HID + k0 + 32 + bseg);
        }

#pragma unroll
        for (int ks = 0; ks < 2; ks++) {
            const int kb = ks * 16;
            uint32_t af[2][4], bf[3][2];
#pragma unroll
            for (int i = 0; i < 2; i++) {
                const int m = wm * 32 + i * 16 + g;
                af[i][0] = *(const uint32_t*)&As2h[m][kb + 2 * t];
                af[i][1] = *(const uint32_t*)&As2h[m + 8][kb + 2 * t];
                af[i][2] = *(const uint32_t*)&As2h[m][kb + 2 * t + 8];
                af[i][3] = *(const uint32_t*)&As2h[m + 8][kb + 2 * t + 8];
            }
#pragma unroll
            for (int j = 0; j < 3; j++) {
                const int n = wn * 24 + j * 8 + g;
                bf[j][0] = *(const uint32_t*)&Bs2h[n][kb + 2 * t];
                bf[j][1] = *(const uint32_t*)&Bs2h[n][kb + 2 * t + 8];
            }
#pragma unroll
            for (int i = 0; i < 2; i++)
#pragma unroll
                for (int j = 0; j < 3; j++)
                    mma_f16(acc[i][j], af[i][0], af[i][1], af[i][2], af[i][3],
                            bf[j][0], bf[j][1]);
        }
        __syncthreads();
    }

#pragma unroll
    for (int i = 0; i < 2; i++) {
        const int r0 = bm + wm * 32 + i * 16 + g;
        const int r1 = r0 + 8;
        const float dv0 = (r0 < M) ? __ldg(g_dinv + r0) : 0.f;
        const float dv1 = (r1 < M) ? __ldg(g_dinv + r1) : 0.f;
#pragma unroll
        for (int j = 0; j < 3; j++) {
            const int gc = wn * 24 + j * 8 + 2 * t;
            const float bz0 = __ldg(bias + gc);
            const float bz1 = __ldg(bias + gc + 1);
            if (r0 < M) {
                float2 v = make_float2(acc[i][j][0] + bz0, acc[i][j][1] + bz1);
                *(float2*)(g_h + (size_t)r0 * D_OUT + gc) = v;
                zbuf[(size_t)r0 * (D_OUT / 2) + gc / 2] =
                    __float22half2_rn(make_float2(dv0 * v.x, dv0 * v.y));
            }
            if (r1 < M) {
                float2 v = make_float2(acc[i][j][2] + bz0, acc[i][j][3] + bz1);
                *(float2*)(g_h + (size_t)r1 * D_OUT + gc) = v;
                zbuf[(size_t)r1 * (D_OUT / 2) + gc / 2] =
                    __float22half2_rn(make_float2(dv1 * v.x, dv1 * v.y));
            }
        }
    }
}

// ---------------------------------------------------------------------------
// Graph preprocessing
// ---------------------------------------------------------------------------
__global__ void convert_idx_kernel(const void* __restrict__ ei_raw) {
    const int* p32 = (const int*)ei_raw;
    bool is64 = true;
#pragma unroll
    for (int i = 0; i < 8; i++) is64 = is64 && (p32[2 * i + 1] == 0);

    int e = blockIdx.x * blockDim.x + threadIdx.x;
    if (e >= N_EDGES) return;
    int s, d;
    if (is64) {
        const long long* p64 = (const long long*)ei_raw;
        s = (int)p64[e];
        d = (int)p64[(size_t)N_EDGES + e];
    } else {
        s = p32[e];
        d = p32[(size_t)N_EDGES + e];
    }
    s = min(max(s, 0), N_NODES - 1);
    d = min(max(d, 0), N_NODES - 1);
    g_src[e] = s;
    g_dst[e] = d;
}

// Fused: zero deg/cursor + transpose W1 -> fp16 [n][k] + W2 -> fp16 [n][k].
__global__ void prep_kernel(const float* __restrict__ W1,
                            const float* __restrict__ W2) {
    int i = blockIdx.x * blockDim.x + threadIdx.x;
    if (i < N_NODES) { g_deg[i] = 0; g_cursor[i] = 0; }
    if (i < W1_ELEMS) {
        const int k = i / D_HID;
        const int n = i % D_HID;
        g_w1t[(size_t)n * D_IN + k] = __float2half(W1[i]);
    }
    if (i < W2_ELEMS) {
        const int k = i / D_OUT;
        const int n = i % D_OUT;
        g_w2t[(size_t)n * D_HID + k] = __float2half(W2[i]);
    }
}

// Convert x to fp16 (vectorized).
__global__ void convert_x_kernel(const float* __restrict__ x) {
    const size_t i = (size_t)(blockIdx.x * blockDim.x + threadIdx.x) * 4;
    if (i >= X_ELEMS) return;
    const float4 v = *(const float4*)(x + i);
    __half2 h0 = __float22half2_rn(make_float2(v.x, v.y));
    __half2 h1 = __float22half2_rn(make_float2(v.z, v.w));
    *(uint2*)(g_xh + i) = make_uint2(*(uint32_t*)&h0, *(uint32_t*)&h1);
}

__global__ void deg_acc_kernel() {
    int e = blockIdx.x * blockDim.x + threadIdx.x;
    if (e < N_EDGES) atomicAdd(&g_deg[g_dst[e]], 1);
}

__global__ __launch_bounds__(256) void blocksum_dinv_kernel() {
    __shared__ int swarp[8];
    const int t = threadIdx.x;
    const int i = blockIdx.x * 256 + t;
    int d = 0;
    if (i < N_NODES) {
        d = g_deg[i];
        g_dinv[i] = rsqrtf((float)(d + 1));   // +1 self-loop
    }
    int v = d;
#pragma unroll
    for (int o = 16; o > 0; o >>= 1) v += __shfl_down_sync(0xffffffffu, v, o);
    if ((t & 31) == 0) swarp[t >> 5] = v;
    __syncthreads();
    if (t == 0) {
        int s = 0;
#pragma unroll
        for (int w = 0; w < 8; w++) s += swarp[w];
        g_bsum[blockIdx.x] = s;
    }
}

__global__ __launch_bounds__(512) void scan_bsums_kernel() {
    __shared__ int sh[512];
    const int t = threadIdx.x;
    sh[t] = (t < NBLK_NODES) ? g_bsum[t] : 0;
    __syncthreads();
#pragma unroll
    for (int off = 1; off < 512; off <<= 1) {
        int v = (t >= off) ? sh[t - off] : 0;
        __syncthreads();
        sh[t] += v;
        __syncthreads();
    }
    if (t < NBLK_NODES) g_bpre[t] = (t == 0) ? 0 : sh[t - 1];
}

__global__ __launch_bounds__(256) void rowptr_kernel() {
    __shared__ int swarp[8];
    const int t = threadIdx.x;
    const int i = blockIdx.x * 256 + t;
    const int lane = t & 31;
    const int w = t >> 5;

    int d = (i < N_NODES) ? g_deg[i] : 0;
    int v = d;
#pragma unroll
    for (int o = 1; o < 32; o <<= 1) {
        int n = __shfl_up_sync(0xffffffffu, v, o);
        if (lane >= o) v += n;
    }
    if (lane == 31) swarp[w] = v;
    __syncthreads();
    if (t == 0) {
        int r = 0;
#pragma unroll
        for (int k = 0; k < 8; k++) { int tmp = swarp[k]; swarp[k] = r; r += tmp; }
    }
    __syncthreads();

    const int excl = g_bpre[blockIdx.x] + swarp[w] + (v - d);
    if (i < N_NODES) {
        g_rowptr[i] = excl;
        if (i == N_NODES - 1) g_rowptr[N_NODES] = excl + d;
    }
}

__global__ void fill_csr_kernel() {
    int e = blockIdx.x * blockDim.x + threadIdx.x;
    if (e >= N_EDGES) return;
    const int s = g_src[e];
    const int d = g_dst[e];
    const int pos = g_rowptr[d] + atomicAdd(&g_cursor[d], 1);
    g_csri[pos] = s;
}

// ---------------------------------------------------------------------------
// Propagation (exact R9 version): z = half2(dinv .* out), 8 threads/node,
// sequential node order, 2-unrolled edge loop.
// ---------------------------------------------------------------------------
__global__ __launch_bounds__(256) void gather_z_kernel(
    const __half2* __restrict__ z, __half2* __restrict__ nxt,
    float* __restrict__ outf, int last)
{
    const int node = blockIdx.x * 32 + (threadIdx.x >> 3);
    const int lane = threadIdx.x & 7;
    if (node >= N_NODES) return;

    const int begin = g_rowptr[node];
    const int end   = g_rowptr[node + 1];

    float2 s0 = make_float2(0.f, 0.f);
    float2 s1 = make_float2(0.f, 0.f);
    float2 s2 = make_float2(0.f, 0.f);

    int e = begin;
    for (; e + 2 <= end; e += 2) {
        const int srcA = __ldg(&g_csri[e]);
        const int srcB = __ldg(&g_csri[e + 1]);
        const __half2* pA = z + (size_t)srcA * (D_OUT / 2) + lane;
        const __half2* pB = z + (size_t)srcB * (D_OUT / 2) + lane;
        const float2 a0 = __half22float2(__ldg(pA));
        const float2 a1 = __half22float2(__ldg(pA + 8));
        const float2 a2 = __half22float2(__ldg(pA + 16));
        const float2 b0 = __half22float2(__ldg(pB));
        const float2 b1 = __half22float2(__ldg(pB + 8));
        const float2 b2 = __half22float2(__ldg(pB + 16));
        s0.x += a0.x + b0.x; s0.y += a0.y + b0.y;
        s1.x += a1.x + b1.x; s1.y += a1.y + b1.y;
        s2.x += a2.x + b2.x; s2.y += a2.y + b2.y;
    }
    if (e < end) {
        const int src = __ldg(&g_csri[e]);
        const __half2* p = z + (size_t)src * (D_OUT / 2) + lane;
        const float2 v0 = __half22float2(__ldg(p));
        const float2 v1 = __half22float2(__ldg(p + 8));
        const float2 v2 = __half22float2(__ldg(p + 16));
        s0.x += v0.x; s0.y += v0.y;
        s1.x += v1.x; s1.y += v1.y;
        s2.x += v2.x; s2.y += v2.y;
    }

    {   // self-loop contribution
        const __half2* p = z + (size_t)node * (D_OUT / 2) + lane;
        const float2 v0 = __half22float2(p[0]);
        const float2 v1 = __half22float2(p[8]);
        const float2 v2 = __half22float2(p[16]);
        s0.x += v0.x; s0.y += v0.y;
        s1.x += v1.x; s1.y += v1.y;
        s2.x += v2.x; s2.y += v2.y;
    }

    const float di = g_dinv[node];
    const float* ph = g_h + (size_t)node * D_OUT + 2 * lane;
    const float2 h0 = *(const float2*)(ph);
    const float2 h1 = *(const float2*)(ph + 16);
    const float2 h2 = *(const float2*)(ph + 32);

    const float w = (1.0f - ALPHA) * di;
    float2 o0 = make_float2(w * s0.x + ALPHA * h0.x, w * s0.y + ALPHA * h0.y);
    float2 o1 = make_float2(w * s1.x + ALPHA * h1.x, w * s1.y + ALPHA * h1.y);
    float2 o2 = make_float2(w * s2.x + ALPHA * h2.x, w * s2.y + ALPHA * h2.y);

    if (last) {
        float* po = outf + (size_t)node * D_OUT + 2 * lane;
        *(float2*)(po)      = o0;
        *(float2*)(po + 16) = o1;
        *(float2*)(po + 32) = o2;
    } else {
        __half2* po = nxt + (size_t)node * (D_OUT / 2) + lane;
        po[0]  = __float22half2_rn(make_float2(di * o0.x, di * o0.y));
        po[8]  = __float22half2_rn(make_float2(di * o1.x, di * o1.y));
        po[16] = __float22half2_rn(make_float2(di * o2.x, di * o2.y));
    }
}

// ---------------------------------------------------------------------------
// Launch. Inputs matched by element count. gemm1 stays at launch slot 3.
// ---------------------------------------------------------------------------
extern "C" void kernel_launch(void* const* d_in, const int* in_sizes, int n_in,
                              void* d_out, int out_size)
{
    const void* x = nullptr; const void* ei = nullptr;
    const void* W1 = nullptr; const void* b1 = nullptr;
    const void* W2 = nullptr; const void* b2 = nullptr;

    for (int i = 0; i < n_in; i++) {
        switch (in_sizes[i]) {
            case 25600000: x  = d_in[i]; break;
            case  3200000: ei = d_in[i]; break;
            case   131072: W1 = d_in[i]; break;
            case      512: b1 = d_in[i]; break;
            case    24576: W2 = d_in[i]; break;
            case       48: b2 = d_in[i]; break;
            default: break;
        }
    }
    if (!x)  x  = d_in[0];
    if (!ei) ei = d_in[1];
    if (!W1) W1 = d_in[2];
    if (!b1) b1 = d_in[3];
    if (!W2) W2 = d_in[4];
    if (!b2) b2 = d_in[5];

    float* out = (float*)d_out;
    const int M = N_NODES;

    __half2* zA;  cudaGetSymbolAddress((void**)&zA, g_zA);
    __half2* zB;  cudaGetSymbolAddress((void**)&zB, g_zB);

    static int smem_set = 0;
    if (!smem_set) {
        cudaFuncSetAttribute(gemm1_tc_kernel,
                             cudaFuncAttributeMaxDynamicSharedMemorySize, G1_SMEM);
        smem_set = 1;
    }

    // 0-2: preprocessing gemm1 needs (x/W1/W2 fp16) + index convert
    convert_idx_kernel<<<(N_EDGES + 255) / 256, 256>>>(ei);
    prep_kernel<<<(W1_ELEMS + 255) / 256, 256>>>((const float*)W1,
                                                 (const float*)W2);
    convert_x_kernel<<<(int)((X_ELEMS / 4 + 255) / 256), 256>>>((const float*)x);

    // 3: GEMM1 fp16 (target of the ncu capture at launch index 3)
    {
        dim3 grid(D_HID / 128, (M + 127) / 128);
        gemm1_tc_kernel<<<grid, 256, G1_SMEM>>>((const float*)b1, M);
    }

    // 4-7: degree accumulate + full-chip scan -> rowptr (+dinv in pass A)
    deg_acc_kernel<<<(N_EDGES + 255) / 256, 256>>>();
    blocksum_dinv_kernel<<<NBLK_NODES, 256>>>();
    scan_bsums_kernel<<<1, 512>>>();
    rowptr_kernel<<<NBLK_NODES, 256>>>();

    // 8: CSR fill (src only)
    fill_csr_kernel<<<(N_EDGES + 255) / 256, 256>>>();

    // 9: GEMM2 fp16 (writes g_h = h fp32 and zA = half2(dinv*h))
    {
        dim3 grid((M + 127) / 128);
        gemm2_tc_kernel<<<grid, 256>>>((const float*)b2, zA, M);
    }

    // 10..19: 10 propagation steps on fp16 z; last step emits fp32 out.
    const int gblocks = (N_NODES + 31) / 32;
    __half2* cur = zA;
    __half2* nxt = zB;
    for (int s = 0; s < K_STEPS; s++) {
        gather_z_kernel<<<gblocks, 256>>>(cur, nxt, out, s == K_STEPS - 1 ? 1 : 0);
        __half2* tmp = cur; cur = nxt; nxt = tmp;
    }
}

// round 16
// speedup vs baseline: 1.3021x; 1.0344x over previous
#include <cuda_runtime.h>
#include <cuda_fp16.h>
#include <cstdint>

// ---------------------------------------------------------------------------
// Problem constants (fixed by the dataset)
// ---------------------------------------------------------------------------
#define N_NODES 100000
#define N_EDGES 1600000
#define D_IN    256
#define D_HID   512
#define D_OUT   48
#define K_STEPS 10
#define ALPHA   0.1f

#define NBLK_NODES ((N_NODES + 255) / 256)   // 391
#define W1_ELEMS  (D_IN * D_HID)             // 131072
#define W2_ELEMS  (D_HID * D_OUT)            // 24576
#define X_ELEMS   ((size_t)N_NODES * D_IN)   // 25,600,000

// ---------------------------------------------------------------------------
// Scratch (static __device__ arrays; no allocation allowed)
// ---------------------------------------------------------------------------
__device__ __align__(16) __half g_hidh[(size_t)N_NODES * D_HID];  // fp16 hid
__device__ __align__(16) float g_h[(size_t)N_NODES * D_OUT];
__device__ __align__(16) __half g_xh[X_ELEMS];                    // fp16 x
__device__ __align__(16) __half g_w1t[W1_ELEMS];                  // W1^T fp16 [512][256]
__device__ __align__(16) __half g_w2t[W2_ELEMS];                  // W2^T fp16 [48][512]
__device__ __align__(16) __half2 g_zA[(size_t)N_NODES * (D_OUT / 2)];
__device__ __align__(16) __half2 g_zB[(size_t)N_NODES * (D_OUT / 2)];
__device__ float g_dinv[N_NODES];
__device__ int   g_deg[N_NODES];
__device__ int   g_cursor[N_NODES];
__device__ int   g_rowptr[N_NODES + 1];
__device__ int   g_bsum[NBLK_NODES];
__device__ int   g_bpre[NBLK_NODES];
__device__ int   g_src[N_EDGES];
__device__ int   g_dst[N_EDGES];
__device__ int   g_csri[N_EDGES];     // CSR: src index only (norm folded into z)

// ---------------------------------------------------------------------------
// mma helper
// ---------------------------------------------------------------------------
__device__ __forceinline__ void mma_f16(float* c,
                                        uint32_t a0, uint32_t a1,
                                        uint32_t a2, uint32_t a3,
                                        uint32_t b0, uint32_t b1) {
    asm volatile(
        "mma.sync.aligned.m16n8k16.row.col.f32.f16.f16.f32 "
        "{%0,%1,%2,%3}, {%4,%5,%6,%7}, {%8,%9}, {%0,%1,%2,%3};"
        : "+f"(c[0]), "+f"(c[1]), "+f"(c[2]), "+f"(c[3])
        : "r"(a0), "r"(a1), "r"(a2), "r"(a3), "r"(b0), "r"(b1));
}

#define CP_ASYNC_16(dst_u32, src_ptr) \
    asm volatile("cp.async.cg.shared.global [%0], [%1], 16;" \
                 :: "r"(dst_u32), "l"(src_ptr))
#define CP_COMMIT() asm volatile("cp.async.commit_group;")
#define CP_WAIT(N)  asm volatile("cp.async.wait_group %0;" :: "n"(N))

// ---------------------------------------------------------------------------
// GEMM1 (fp16): g_hidh = half(relu(x @ W1 + b1)), fp16 m16n8k16, fp32 acc.
// (unchanged from R15)
// ---------------------------------------------------------------------------
#define A16_STRIDE 40
#define A16_STAGE (128 * A16_STRIDE)        // 5120 halves
#define B16_STAGE (128 * A16_STRIDE)
#define G1_SMEM ((3 * A16_STAGE + 3 * B16_STAGE) * 2)   // 61440 bytes
#define N_CHUNK16 (D_IN / 32)               // 8

__global__ __launch_bounds__(256, 2) void gemm1_tc_kernel(
    const float* __restrict__ bias, // [512]
    int M)
{
    extern __shared__ __half smemh[];
    __half* AsB = smemh;
    __half* BsB = smemh + 3 * A16_STAGE;

    const int tid = threadIdx.x;
    const int bn = blockIdx.x * 128;
    const int bm = blockIdx.y * 128;

    const int wid = tid >> 5;
    const int lane = tid & 31;
    const int g = lane >> 2;
    const int t = lane & 3;
    const int wm = wid & 1;
    const int wn = wid >> 1;

    float acc[4][4][4];
#pragma unroll
    for (int i = 0; i < 4; i++)
#pragma unroll
        for (int j = 0; j < 4; j++)
#pragma unroll
            for (int q = 0; q < 4; q++) acc[i][j][q] = 0.0f;

    uint32_t aDst[2], bDst[2];
    const __half* aSrc[2];
    const __half* bSrc[2];
    {
        const uint32_t asBase = (uint32_t)__cvta_generic_to_shared(AsB);
        const uint32_t bsBase = (uint32_t)__cvta_generic_to_shared(BsB);
#pragma unroll
        for (int q = 0; q < 2; q++) {
            const int idx = tid + 256 * q;
            const int row = idx >> 2;
            const int seg = (idx & 3) * 8;
            aDst[q] = asBase + (row * A16_STRIDE + seg) * 2;
            const int gr = min(bm + row, M - 1);
            aSrc[q] = g_xh + (size_t)gr * D_IN + seg;
            bDst[q] = bsBase + (row * A16_STRIDE + seg) * 2;
            bSrc[q] = g_w1t + (size_t)(bn + row) * D_IN + seg;
        }
    }

#pragma unroll
    for (int q = 0; q < 2; q++) {
        CP_ASYNC_16(aDst[q], aSrc[q]);
        CP_ASYNC_16(bDst[q], bSrc[q]);
    }
    CP_COMMIT();
#pragma unroll
    for (int q = 0; q < 2; q++) {
        CP_ASYNC_16(aDst[q] + A16_STAGE * 2, aSrc[q] + 32);
        CP_ASYNC_16(bDst[q] + B16_STAGE * 2, bSrc[q] + 32);
    }
    CP_COMMIT();

    int stC = 0;
    for (int ch = 0; ch < N_CHUNK16; ch++) {
        if (ch < N_CHUNK16 - 1) { CP_WAIT(1); } else { CP_WAIT(0); }
        __syncthreads();

        const __half* As = AsB + stC * A16_STAGE;
        const __half* Bs = BsB + stC * B16_STAGE;
#pragma unroll
        for (int ks = 0; ks < 2; ks++) {
            const int kb = ks * 16;
            uint32_t af[4][4], bf[4][2];
#pragma unroll
            for (int i = 0; i < 4; i++) {
                const int m = wm * 64 + i * 16 + g;
                af[i][0] = *(const uint32_t*)&As[m * A16_STRIDE + kb + 2 * t];
                af[i][1] = *(const uint32_t*)&As[(m + 8) * A16_STRIDE + kb + 2 * t];
                af[i][2] = *(const uint32_t*)&As[m * A16_STRIDE + kb + 2 * t + 8];
                af[i][3] = *(const uint32_t*)&As[(m + 8) * A16_STRIDE + kb + 2 * t + 8];
            }
#pragma unroll
            for (int j = 0; j < 4; j++) {
                const int n = wn * 32 + j * 8 + g;
                bf[j][0] = *(const uint32_t*)&Bs[n * A16_STRIDE + kb + 2 * t];
                bf[j][1] = *(const uint32_t*)&Bs[n * A16_STRIDE + kb + 2 * t + 8];
            }
#pragma unroll
            for (int i = 0; i < 4; i++)
#pragma unroll
                for (int j = 0; j < 4; j++)
                    mma_f16(acc[i][j], af[i][0], af[i][1], af[i][2], af[i][3],
                            bf[j][0], bf[j][1]);
        }

        if (ch + 2 < N_CHUNK16) {
            const int stP = (stC + 2 >= 3) ? stC - 1 : stC + 2;
            const int ko = (ch + 2) * 32;
#pragma unroll
            for (int q = 0; q < 2; q++) {
                CP_ASYNC_16(aDst[q] + stP * A16_STAGE * 2, aSrc[q] + ko);
                CP_ASYNC_16(bDst[q] + stP * B16_STAGE * 2, bSrc[q] + ko);
            }
            CP_COMMIT();
        }
        stC = (stC + 1 == 3) ? 0 : stC + 1;
    }

#pragma unroll
    for (int i = 0; i < 4; i++) {
        const int r0 = bm + wm * 64 + i * 16 + g;
        const int r1 = r0 + 8;
#pragma unroll
        for (int j = 0; j < 4; j++) {
            const int gc = bn + wn * 32 + j * 8 + 2 * t;
            const float bz0 = __ldg(bias + gc);
            const float bz1 = __ldg(bias + gc + 1);
            if (r0 < M) {
                *(__half2*)(g_hidh + (size_t)r0 * D_HID + gc) =
                    __float22half2_rn(make_float2(fmaxf(acc[i][j][0] + bz0, 0.f),
                                                  fmaxf(acc[i][j][1] + bz1, 0.f)));
            }
            if (r1 < M) {
                *(__half2*)(g_hidh + (size_t)r1 * D_HID + gc) =
                    __float22half2_rn(make_float2(fmaxf(acc[i][j][2] + bz0, 0.f),
                                                  fmaxf(acc[i][j][3] + bz1, 0.f)));
            }
        }
    }
}

// ---------------------------------------------------------------------------
// GEMM2 (fp16): h = hid @ W2 + b2. (unchanged from R15)
// ---------------------------------------------------------------------------
#define A2S 40

__global__ __launch_bounds__(256) void gemm2_tc_kernel(
    const float* __restrict__ bias, // [48]
    __half2* __restrict__ zbuf,     // [M, 24]
    int M)
{
    __shared__ __align__(16) __half As2h[128][A2S];
    __shared__ __align__(16) __half Bs2h[48][A2S];

    const int tid = threadIdx.x;
    const int bm = blockIdx.x * 128;

    const int wid = tid >> 5;
    const int lane = tid & 31;
    const int g = lane >> 2;
    const int t = lane & 3;
    const int wm = wid & 3;
    const int wn = wid >> 2;

    const int aRow = tid >> 1;
    const int aCol = (tid & 1) * 16;
    const int gr = min(bm + aRow, M - 1);

    const int bn48 = tid >> 2;
    const int bseg = (tid & 3) * 8;

    float acc[2][3][4];
#pragma unroll
    for (int i = 0; i < 2; i++)
#pragma unroll
        for (int j = 0; j < 3; j++)
#pragma unroll
            for (int q = 0; q < 4; q++) acc[i][j][q] = 0.0f;

    uint4 aPre[2];
    uint4 bPre = make_uint4(0, 0, 0, 0);
    aPre[0] = *(const uint4*)(g_hidh + (size_t)gr * D_HID + aCol);
    aPre[1] = *(const uint4*)(g_hidh + (size_t)gr * D_HID + aCol + 8);
    if (bn48 < 48)
        bPre = *(const uint4*)(g_w2t + (size_t)bn48 * D_HID + bseg);

    for (int k0 = 0; k0 < D_HID; k0 += 32) {
        *(uint4*)&As2h[aRow][aCol]     = aPre[0];
        *(uint4*)&As2h[aRow][aCol + 8] = aPre[1];
        if (bn48 < 48)
            *(uint4*)&Bs2h[bn48][bseg] = bPre;
        __syncthreads();

        if (k0 + 32 < D_HID) {
            aPre[0] = *(const uint4*)(g_hidh + (size_t)gr * D_HID + k0 + 32 + aCol);
            aPre[1] = *(const uint4*)(g_hidh + (size_t)gr * D_HID + k0 + 32 + aCol + 8);
            if (bn48 < 48)
                bPre = *(const uint4*)(g_w2t + (size_t)bn48 * D_HID + k0 + 32 + bseg);
        }

#pragma unroll
        for (int ks = 0; ks < 2; ks++) {
            const int kb = ks * 16;
            uint32_t af[2][4], bf[3][2];
#pragma unroll
            for (int i = 0; i < 2; i++) {
                const int m = wm * 32 + i * 16 + g;
                af[i][0] = *(const uint32_t*)&As2h[m][kb + 2 * t];
                af[i][1] = *(const uint32_t*)&As2h[m + 8][kb + 2 * t];
                af[i][2] = *(const uint32_t*)&As2h[m][kb + 2 * t + 8];
                af[i][3] = *(const uint32_t*)&As2h[m + 8][kb + 2 * t + 8];
            }
#pragma unroll
            for (int j = 0; j < 3; j++) {
                const int n = wn * 24 + j * 8 + g;
                bf[j][0] = *(const uint32_t*)&Bs2h[n][kb + 2 * t];
                bf[j][1] = *(const uint32_t*)&Bs2h[n][kb + 2 * t + 8];
            }
#pragma unroll
            for (int i = 0; i < 2; i++)
#pragma unroll
                for (int j = 0; j < 3; j++)
                    mma_f16(acc[i][j], af[i][0], af[i][1], af[i][2], af[i][3],
                            bf[j][0], bf[j][1]);
        }
        __syncthreads();
    }

#pragma unroll
    for (int i = 0; i < 2; i++) {
        const int r0 = bm + wm * 32 + i * 16 + g;
        const int r1 = r0 + 8;
        const float dv0 = (r0 < M) ? __ldg(g_dinv + r0) : 0.f;
        const float dv1 = (r1 < M) ? __ldg(g_dinv + r1) : 0.f;
#pragma unroll
        for (int j = 0; j < 3; j++) {
            const int gc = wn * 24 + j * 8 + 2 * t;
            const float bz0 = __ldg(bias + gc);
            const float bz1 = __ldg(bias + gc + 1);
            if (r0 < M) {
                float2 v = make_float2(acc[i][j][0] + bz0, acc[i][j][1] + bz1);
                *(float2*)(g_h + (size_t)r0 * D_OUT + gc) = v;
                zbuf[(size_t)r0 * (D_OUT / 2) + gc / 2] =
                    __float22half2_rn(make_float2(dv0 * v.x, dv0 * v.y));
            }
            if (r1 < M) {
                float2 v = make_float2(acc[i][j][2] + bz0, acc[i][j][3] + bz1);
                *(float2*)(g_h + (size_t)r1 * D_OUT + gc) = v;
                zbuf[(size_t)r1 * (D_OUT / 2) + gc / 2] =
                    __float22half2_rn(make_float2(dv1 * v.x, dv1 * v.y));
            }
        }
    }
}

// ---------------------------------------------------------------------------
// Graph preprocessing
// ---------------------------------------------------------------------------
// Fused: zero deg/cursor + transpose W1 -> fp16 [n][k] + W2 -> fp16 [n][k].
// MUST run before convert_idx (which accumulates degrees).
__global__ void prep_kernel(const float* __restrict__ W1,
                            const float* __restrict__ W2) {
    int i = blockIdx.x * blockDim.x + threadIdx.x;
    if (i < N_NODES) { g_deg[i] = 0; g_cursor[i] = 0; }
    if (i < W1_ELEMS) {
        const int k = i / D_HID;
        const int n = i % D_HID;
        g_w1t[(size_t)n * D_IN + k] = __float2half(W1[i]);
    }
    if (i < W2_ELEMS) {
        const int k = i / D_OUT;
        const int n = i % D_OUT;
        g_w2t[(size_t)n * D_HID + k] = __float2half(W2[i]);
    }
}

// Fused: index convert + degree accumulate (one edge pass instead of two).
__global__ void convert_idx_kernel(const void* __restrict__ ei_raw) {
    const int* p32 = (const int*)ei_raw;
    bool is64 = true;
#pragma unroll
    for (int i = 0; i < 8; i++) is64 = is64 && (p32[2 * i + 1] == 0);

    int e = blockIdx.x * blockDim.x + threadIdx.x;
    if (e >= N_EDGES) return;
    int s, d;
    if (is64) {
        const long long* p64 = (const long long*)ei_raw;
        s = (int)p64[e];
        d = (int)p64[(size_t)N_EDGES + e];
    } else {
        s = p32[e];
        d = p32[(size_t)N_EDGES + e];
    }
    s = min(max(s, 0), N_NODES - 1);
    d = min(max(d, 0), N_NODES - 1);
    g_src[e] = s;
    g_dst[e] = d;
    atomicAdd(&g_deg[d], 1);
}

// Convert x to fp16 (vectorized).
__global__ void convert_x_kernel(const float* __restrict__ x) {
    const size_t i = (size_t)(blockIdx.x * blockDim.x + threadIdx.x) * 4;
    if (i >= X_ELEMS) return;
    const float4 v = *(const float4*)(x + i);
    __half2 h0 = __float22half2_rn(make_float2(v.x, v.y));
    __half2 h1 = __float22half2_rn(make_float2(v.z, v.w));
    *(uint2*)(g_xh + i) = make_uint2(*(uint32_t*)&h0, *(uint32_t*)&h1);
}

__global__ __launch_bounds__(256) void blocksum_dinv_kernel() {
    __shared__ int swarp[8];
    const int t = threadIdx.x;
    const int i = blockIdx.x * 256 + t;
    int d = 0;
    if (i < N_NODES) {
        d = g_deg[i];
        g_dinv[i] = rsqrtf((float)(d + 1));   // +1 self-loop
    }
    int v = d;
#pragma unroll
    for (int o = 16; o > 0; o >>= 1) v += __shfl_down_sync(0xffffffffu, v, o);
    if ((t & 31) == 0) swarp[t >> 5] = v;
    __syncthreads();
    if (t == 0) {
        int s = 0;
#pragma unroll
        for (int w = 0; w < 8; w++) s += swarp[w];
        g_bsum[blockIdx.x] = s;
    }
}

__global__ __launch_bounds__(512) void scan_bsums_kernel() {
    __shared__ int sh[512];
    const int t = threadIdx.x;
    sh[t] = (t < NBLK_NODES) ? g_bsum[t] : 0;
    __syncthreads();
#pragma unroll
    for (int off = 1; off < 512; off <<= 1) {
        int v = (t >= off) ? sh[t - off] : 0;
        __syncthreads();
        sh[t] += v;
        __syncthreads();
    }
    if (t < NBLK_NODES) g_bpre[t] = (t == 0) ? 0 : sh[t - 1];
}

__global__ __launch_bounds__(256) void rowptr_kernel() {
    __shared__ int swarp[8];
    const int t = threadIdx.x;
    const int i = blockIdx.x * 256 + t;
    const int lane = t & 31;
    const int w = t >> 5;

    int d = (i < N_NODES) ? g_deg[i] : 0;
    int v = d;
#pragma unroll
    for (int o = 1; o < 32; o <<= 1) {
        int n = __shfl_up_sync(0xffffffffu, v, o);
        if (lane >= o) v += n;
    }
    if (lane == 31) swarp[w] = v;
    __syncthreads();
    if (t == 0) {
        int r = 0;
#pragma unroll
        for (int k = 0; k < 8; k++) { int tmp = swarp[k]; swarp[k] = r; r += tmp; }
    }
    __syncthreads();

    const int excl = g_bpre[blockIdx.x] + swarp[w] + (v - d);
    if (i < N_NODES) {
        g_rowptr[i] = excl;
        if (i == N_NODES - 1) g_rowptr[N_NODES] = excl + d;
    }
}

__global__ void fill_csr_kernel() {
    int e = blockIdx.x * blockDim.x + threadIdx.x;
    if (e >= N_EDGES) return;
    const int s = g_src[e];
    const int d = g_dst[e];
    const int pos = g_rowptr[d] + atomicAdd(&g_cursor[d], 1);
    g_csri[pos] = s;
}

// ---------------------------------------------------------------------------
// Propagation: z = half2(dinv .* out), 8 threads/node (sequential nodes).
// Lanes 0-5 each own a 16B slice of the 96B row: ONE uint4 LDG per edge
// (halves warp-LDG issue count vs half2 loads; gather is LSU-issue-bound).
// ---------------------------------------------------------------------------
__global__ __launch_bounds__(256) void gather_z_kernel(
    const __half2* __restrict__ z, __half2* __restrict__ nxt,
    float* __restrict__ outf, int last)
{
    const int node = blockIdx.x * 32 + (threadIdx.x >> 3);
    const int lane = threadIdx.x & 7;
    if (node >= N_NODES || lane >= 6) return;   // lanes 6,7 idle

    const int begin = __ldg(&g_rowptr[node]);
    const int end   = __ldg(&g_rowptr[node + 1]);

    const char* zb = (const char*)z;
    const size_t lOff = (size_t)lane * 16;

    float2 s0 = make_float2(0.f, 0.f);
    float2 s1 = make_float2(0.f, 0.f);
    float2 s2 = make_float2(0.f, 0.f);
    float2 s3 = make_float2(0.f, 0.f);

    int e = begin;
    for (; e + 2 <= end; e += 2) {
        const int srcA = __ldg(&g_csri[e]);
        const int srcB = __ldg(&g_csri[e + 1]);
        const uint4 va = __ldg((const uint4*)(zb + (size_t)srcA * 96 + lOff));
        const uint4 vb = __ldg((const uint4*)(zb + (size_t)srcB * 96 + lOff));
        const __half2* ha = (const __half2*)&va;
        const __half2* hb = (const __half2*)&vb;
        float2 f;
        f = __half22float2(ha[0]); s0.x += f.x; s0.y += f.y;
        f = __half22float2(ha[1]); s1.x += f.x; s1.y += f.y;
        f = __half22float2(ha[2]); s2.x += f.x; s2.y += f.y;
        f = __half22float2(ha[3]); s3.x += f.x; s3.y += f.y;
        f = __half22float2(hb[0]); s0.x += f.x; s0.y += f.y;
        f = __half22float2(hb[1]); s1.x += f.x; s1.y += f.y;
        f = __half22float2(hb[2]); s2.x += f.x; s2.y += f.y;
        f = __half22float2(hb[3]); s3.x += f.x; s3.y += f.y;
    }
    if (e < end) {
        const int src = __ldg(&g_csri[e]);
        const uint4 v = __ldg((const uint4*)(zb + (size_t)src * 96 + lOff));
        const __half2* hv = (const __half2*)&v;
        float2 f;
        f = __half22float2(hv[0]); s0.x += f.x; s0.y += f.y;
        f = __half22float2(hv[1]); s1.x += f.x; s1.y += f.y;
        f = __half22float2(hv[2]); s2.x += f.x; s2.y += f.y;
        f = __half22float2(hv[3]); s3.x += f.x; s3.y += f.y;
    }

    {   // self-loop contribution
        const uint4 v = *(const uint4*)(zb + (size_t)node * 96 + lOff);
        const __half2* hv = (const __half2*)&v;
        float2 f;
        f = __half22float2(hv[0]); s0.x += f.x; s0.y += f.y;
        f = __half22float2(hv[1]); s1.x += f.x; s1.y += f.y;
        f = __half22float2(hv[2]); s2.x += f.x; s2.y += f.y;
        f = __half22float2(hv[3]); s3.x += f.x; s3.y += f.y;
    }

    const float di = __ldg(&g_dinv[node]);
    const float* ph = g_h + (size_t)node * D_OUT + lane * 8;
    const float4 hA = *(const float4*)(ph);
    const float4 hB = *(const float4*)(ph + 4);

    const float w = (1.0f - ALPHA) * di;
    float4 oA, oB;
    oA.x = w * s0.x + ALPHA * hA.x;  oA.y = w * s0.y + ALPHA * hA.y;
    oA.z = w * s1.x + ALPHA * hA.z;  oA.w = w * s1.y + ALPHA * hA.w;
    oB.x = w * s2.x + ALPHA * hB.x;  oB.y = w * s2.y + ALPHA * hB.y;
    oB.z = w * s3.x + ALPHA * hB.z;  oB.w = w * s3.y + ALPHA * hB.w;

    if (last) {
        float* po = outf + (size_t)node * D_OUT + lane * 8;
        *(float4*)(po)     = oA;
        *(float4*)(po + 4) = oB;
    } else {
        uint4 pk;
        __half2* hp = (__half2*)&pk;
        hp[0] = __float22half2_rn(make_float2(di * oA.x, di * oA.y));
        hp[1] = __float22half2_rn(make_float2(di * oA.z, di * oA.w));
        hp[2] = __float22half2_rn(make_float2(di * oB.x, di * oB.y));
        hp[3] = __float22half2_rn(make_float2(di * oB.z, di * oB.w));
        *(uint4*)((char*)nxt + (size_t)node * 96 + lOff) = pk;
    }
}

// ---------------------------------------------------------------------------
// Launch. Inputs matched by element count. gemm1 stays at launch slot 3.
// ---------------------------------------------------------------------------
extern "C" void kernel_launch(void* const* d_in, const int* in_sizes, int n_in,
                              void* d_out, int out_size)
{
    const void* x = nullptr; const void* ei = nullptr;
    const void* W1 = nullptr; const void* b1 = nullptr;
    const void* W2 = nullptr; const void* b2 = nullptr;

    for (int i = 0; i < n_in; i++) {
        switch (in_sizes[i]) {
            case 25600000: x  = d_in[i]; break;
            case  3200000: ei = d_in[i]; break;
            case   131072: W1 = d_in[i]; break;
            case      512: b1 = d_in[i]; break;
            case    24576: W2 = d_in[i]; break;
            case       48: b2 = d_in[i]; break;
            default: break;
        }
    }
    if (!x)  x  = d_in[0];
    if (!ei) ei = d_in[1];
    if (!W1) W1 = d_in[2];
    if (!b1) b1 = d_in[3];
    if (!W2) W2 = d_in[4];
    if (!b2) b2 = d_in[5];

    float* out = (float*)d_out;
    const int M = N_NODES;

    __half2* zA;  cudaGetSymbolAddress((void**)&zA, g_zA);
    __half2* zB;  cudaGetSymbolAddress((void**)&zB, g_zB);

    static int smem_set = 0;
    if (!smem_set) {
        cudaFuncSetAttribute(gemm1_tc_kernel,
                             cudaFuncAttributeMaxDynamicSharedMemorySize, G1_SMEM);
        smem_set = 1;
    }

    // 0: zero deg/cursor + W1/W2 fp16 transposes (before convert_idx!)
    prep_kernel<<<(W1_ELEMS + 255) / 256, 256>>>((const float*)W1,
                                                 (const float*)W2);
    // 1: index convert + degree accumulate (fused)
    convert_idx_kernel<<<(N_EDGES + 255) / 256, 256>>>(ei);
    // 2: x -> fp16
    convert_x_kernel<<<(int)((X_ELEMS / 4 + 255) / 256), 256>>>((const float*)x);

    // 3: GEMM1 fp16 (target of the ncu capture at launch index 3)
    {
        dim3 grid(D_HID / 128, (M + 127) / 128);
        gemm1_tc_kernel<<<grid, 256, G1_SMEM>>>((const float*)b1, M);
    }

    // 4-6: full-chip scan -> rowptr (+dinv folded into pass A)
    blocksum_dinv_kernel<<<NBLK_NODES, 256>>>();
    scan_bsums_kernel<<<1, 512>>>();
    rowptr_kernel<<<NBLK_NODES, 256>>>();

    // 7: CSR fill (src only)
    fill_csr_kernel<<<(N_EDGES + 255) / 256, 256>>>();

    // 8: GEMM2 fp16 (writes g_h = h fp32 and zA = half2(dinv*h))
    {
        dim3 grid((M + 127) / 128);
        gemm2_tc_kernel<<<grid, 256>>>((const float*)b2, zA, M);
    }

    // 9..18: 10 propagation steps on fp16 z; last step emits fp32 out.
    const int gblocks = (N_NODES + 31) / 32;
    __half2* cur = zA;
    __half2* nxt = zB;
    for (int s = 0; s < K_STEPS; s++) {
        gather_z_kernel<<<gblocks, 256>>>(cur, nxt, out, s == K_STEPS - 1 ? 1 : 0);
        __half2* tmp = cur; cur = nxt; nxt = tmp;
    }
}

// round 17
// speedup vs baseline: 1.3445x; 1.0326x over previous
#include <cuda_runtime.h>
#include <cuda_fp16.h>
#include <cstdint>

// ---------------------------------------------------------------------------
// Problem constants (fixed by the dataset)
// ---------------------------------------------------------------------------
#define N_NODES 100000
#define N_EDGES 1600000
#define D_IN    256
#define D_HID   512
#define D_OUT   48
#define K_STEPS 10
#define ALPHA   0.1f

#define NBLK_NODES ((N_NODES + 255) / 256)   // 391
#define W1_ELEMS  (D_IN * D_HID)             // 131072
#define W2_ELEMS  (D_HID * D_OUT)            // 24576
#define X_ELEMS   ((size_t)N_NODES * D_IN)   // 25,600,000

// ---------------------------------------------------------------------------
// Scratch (static __device__ arrays; no allocation allowed)
// ---------------------------------------------------------------------------
__device__ __align__(16) __half g_hidh[(size_t)N_NODES * D_HID];  // fp16 hid
__device__ __align__(16) float g_h[(size_t)N_NODES * D_OUT];
__device__ __align__(16) __half g_xh[X_ELEMS];                    // fp16 x
__device__ __align__(16) __half g_w1t[W1_ELEMS];                  // W1^T fp16 [512][256]
__device__ __align__(16) __half g_w2t[W2_ELEMS];                  // W2^T fp16 [48][512]
__device__ __align__(16) __half2 g_zA[(size_t)N_NODES * (D_OUT / 2)];
__device__ __align__(16) __half2 g_zB[(size_t)N_NODES * (D_OUT / 2)];
__device__ float g_dinv[N_NODES];
__device__ int   g_deg[N_NODES];
__device__ int   g_cursor[N_NODES];
__device__ int   g_rowptr[N_NODES + 1];
__device__ int   g_bsum[NBLK_NODES];
__device__ int   g_bpre[NBLK_NODES];
__device__ int   g_src[N_EDGES];
__device__ int   g_dst[N_EDGES];
__device__ int   g_csri[N_EDGES];     // CSR: src index only (norm folded into z)

// ---------------------------------------------------------------------------
// mma / ldmatrix helpers
// ---------------------------------------------------------------------------
__device__ __forceinline__ void mma_f16(float* c,
                                        uint32_t a0, uint32_t a1,
                                        uint32_t a2, uint32_t a3,
                                        uint32_t b0, uint32_t b1) {
    asm volatile(
        "mma.sync.aligned.m16n8k16.row.col.f32.f16.f16.f32 "
        "{%0,%1,%2,%3}, {%4,%5,%6,%7}, {%8,%9}, {%0,%1,%2,%3};"
        : "+f"(c[0]), "+f"(c[1]), "+f"(c[2]), "+f"(c[3])
        : "r"(a0), "r"(a1), "r"(a2), "r"(a3), "r"(b0), "r"(b1));
}

#define LDSM4(d0, d1, d2, d3, a) \
    asm volatile("ldmatrix.sync.aligned.m8n8.x4.shared.b16 {%0,%1,%2,%3}, [%4];" \
        : "=r"(d0), "=r"(d1), "=r"(d2), "=r"(d3) : "r"(a))

#define CP_ASYNC_16(dst_u32, src_ptr) \
    asm volatile("cp.async.cg.shared.global [%0], [%1], 16;" \
                 :: "r"(dst_u32), "l"(src_ptr))
#define CP_COMMIT() asm volatile("cp.async.commit_group;")
#define CP_WAIT(N)  asm volatile("cp.async.wait_group %0;" :: "n"(N))

// ---------------------------------------------------------------------------
// GEMM1 (fp16): g_hidh = half(relu(x @ W1 + b1)), fp16 m16n8k16, fp32 acc.
// R15 structure; fragment loads now via ldmatrix.x4 (6 LDSM per k-slice
// instead of 24 LDS.32 -> fewer scoreboard arms per MMA chain).
// ---------------------------------------------------------------------------
#define A16_STRIDE 40
#define A16_STAGE (128 * A16_STRIDE)        // 5120 halves
#define B16_STAGE (128 * A16_STRIDE)
#define G1_SMEM ((3 * A16_STAGE + 3 * B16_STAGE) * 2)   // 61440 bytes
#define N_CHUNK16 (D_IN / 32)               // 8

__global__ __launch_bounds__(256, 2) void gemm1_tc_kernel(
    const float* __restrict__ bias, // [512]
    int M)
{
    extern __shared__ __half smemh[];
    __half* AsB = smemh;
    __half* BsB = smemh + 3 * A16_STAGE;

    const int tid = threadIdx.x;
    const int bn = blockIdx.x * 128;
    const int bm = blockIdx.y * 128;

    const int wid = tid >> 5;
    const int lane = tid & 31;
    const int g = lane >> 2;
    const int t = lane & 3;
    const int wm = wid & 1;
    const int wn = wid >> 1;

    // ldmatrix lane-address selectors
    const int l8 = lane & 7;
    const int aRowSel = ((lane >> 3) & 1) * 8;   // +0 / +8 rows (m)
    const int aColSel = (lane >> 4) * 8;         // +0 / +8 cols (k)
    const int bMi = lane >> 3;                   // 0..3
    const int bRowSel = (bMi >> 1) * 8;          // +0 / +8 rows (n)
    const int bColSel = (bMi & 1) * 8;           // +0 / +8 cols (k)

    float acc[4][4][4];
#pragma unroll
    for (int i = 0; i < 4; i++)
#pragma unroll
        for (int j = 0; j < 4; j++)
#pragma unroll
            for (int q = 0; q < 4; q++) acc[i][j][q] = 0.0f;

    uint32_t aDst[2], bDst[2];
    const __half* aSrc[2];
    const __half* bSrc[2];
    const uint32_t asBase = (uint32_t)__cvta_generic_to_shared(AsB);
    const uint32_t bsBase = (uint32_t)__cvta_generic_to_shared(BsB);
    {
#pragma unroll
        for (int q = 0; q < 2; q++) {
            const int idx = tid + 256 * q;
            const int row = idx >> 2;
            const int seg = (idx & 3) * 8;
            aDst[q] = asBase + (row * A16_STRIDE + seg) * 2;
            const int gr = min(bm + row, M - 1);
            aSrc[q] = g_xh + (size_t)gr * D_IN + seg;
            bDst[q] = bsBase + (row * A16_STRIDE + seg) * 2;
            bSrc[q] = g_w1t + (size_t)(bn + row) * D_IN + seg;
        }
    }

#pragma unroll
    for (int q = 0; q < 2; q++) {
        CP_ASYNC_16(aDst[q], aSrc[q]);
        CP_ASYNC_16(bDst[q], bSrc[q]);
    }
    CP_COMMIT();
#pragma unroll
    for (int q = 0; q < 2; q++) {
        CP_ASYNC_16(aDst[q] + A16_STAGE * 2, aSrc[q] + 32);
        CP_ASYNC_16(bDst[q] + B16_STAGE * 2, bSrc[q] + 32);
    }
    CP_COMMIT();

    int stC = 0;
    for (int ch = 0; ch < N_CHUNK16; ch++) {
        if (ch < N_CHUNK16 - 1) { CP_WAIT(1); } else { CP_WAIT(0); }
        __syncthreads();

        const uint32_t asS = asBase + stC * A16_STAGE * 2;
        const uint32_t bsS = bsBase + stC * B16_STAGE * 2;
#pragma unroll
        for (int ks = 0; ks < 2; ks++) {
            const int kb = ks * 16;
            uint32_t af[4][4], bf[4][2];
            // A fragments: 4 x ldmatrix.x4 (16x16 tile each)
#pragma unroll
            for (int i = 0; i < 4; i++) {
                const int m = wm * 64 + i * 16 + aRowSel + l8;
                const uint32_t addr = asS + (m * A16_STRIDE + kb + aColSel) * 2;
                LDSM4(af[i][0], af[i][1], af[i][2], af[i][3], addr);
            }
            // B fragments: 2 x ldmatrix.x4 (two n8-pairs each)
#pragma unroll
            for (int p = 0; p < 2; p++) {
                const int n = wn * 32 + p * 16 + bRowSel + l8;
                const uint32_t addr = bsS + (n * A16_STRIDE + kb + bColSel) * 2;
                LDSM4(bf[2 * p][0], bf[2 * p][1], bf[2 * p + 1][0], bf[2 * p + 1][1], addr);
            }
#pragma unroll
            for (int i = 0; i < 4; i++)
#pragma unroll
                for (int j = 0; j < 4; j++)
                    mma_f16(acc[i][j], af[i][0], af[i][1], af[i][2], af[i][3],
                            bf[j][0], bf[j][1]);
        }

        if (ch + 2 < N_CHUNK16) {
            const int stP = (stC + 2 >= 3) ? stC - 1 : stC + 2;
            const int ko = (ch + 2) * 32;
#pragma unroll
            for (int q = 0; q < 2; q++) {
                CP_ASYNC_16(aDst[q] + stP * A16_STAGE * 2, aSrc[q] + ko);
                CP_ASYNC_16(bDst[q] + stP * B16_STAGE * 2, bSrc[q] + ko);
            }
            CP_COMMIT();
        }
        stC = (stC + 1 == 3) ? 0 : stC + 1;
    }

    // epilogue: bias + relu -> fp16 store
#pragma unroll
    for (int i = 0; i < 4; i++) {
        const int r0 = bm + wm * 64 + i * 16 + g;
        const int r1 = r0 + 8;
#pragma unroll
        for (int j = 0; j < 4; j++) {
            const int gc = bn + wn * 32 + j * 8 + 2 * t;
            const float bz0 = __ldg(bias + gc);
            const float bz1 = __ldg(bias + gc + 1);
            if (r0 < M) {
                *(__half2*)(g_hidh + (size_t)r0 * D_HID + gc) =
                    __float22half2_rn(make_float2(fmaxf(acc[i][j][0] + bz0, 0.f),
                                                  fmaxf(acc[i][j][1] + bz1, 0.f)));
            }
            if (r1 < M) {
                *(__half2*)(g_hidh + (size_t)r1 * D_HID + gc) =
                    __float22half2_rn(make_float2(fmaxf(acc[i][j][2] + bz0, 0.f),
                                                  fmaxf(acc[i][j][3] + bz1, 0.f)));
            }
        }
    }
}

// ---------------------------------------------------------------------------
// GEMM2 (fp16): h = hid @ W2 + b2. (unchanged from R15/R16)
// ---------------------------------------------------------------------------
#define A2S 40

__global__ __launch_bounds__(256) void gemm2_tc_kernel(
    const float* __restrict__ bias, // [48]
    __half2* __restrict__ zbuf,     // [M, 24]
    int M)
{
    __shared__ __align__(16) __half As2h[128][A2S];
    __shared__ __align__(16) __half Bs2h[48][A2S];

    const int tid = threadIdx.x;
    const int bm = blockIdx.x * 128;

    const int wid = tid >> 5;
    const int lane = tid & 31;
    const int g = lane >> 2;
    const int t = lane & 3;
    const int wm = wid & 3;
    const int wn = wid >> 2;

    const int aRow = tid >> 1;
    const int aCol = (tid & 1) * 16;
    const int gr = min(bm + aRow, M - 1);

    const int bn48 = tid >> 2;
    const int bseg = (tid & 3) * 8;

    float acc[2][3][4];
#pragma unroll
    for (int i = 0; i < 2; i++)
#pragma unroll
        for (int j = 0; j < 3; j++)
#pragma unroll
            for (int q = 0; q < 4; q++) acc[i][j][q] = 0.0f;

    uint4 aPre[2];
    uint4 bPre = make_uint4(0, 0, 0, 0);
    aPre[0] = *(const uint4*)(g_hidh + (size_t)gr * D_HID + aCol);
    aPre[1] = *(const uint4*)(g_hidh + (size_t)gr * D_HID + aCol + 8);
    if (bn48 < 48)
        bPre = *(const uint4*)(g_w2t + (size_t)bn48 * D_HID + bseg);

    for (int k0 = 0; k0 < D_HID; k0 += 32) {
        *(uint4*)&As2h[aRow][aCol]     = aPre[0];
        *(uint4*)&As2h[aRow][aCol + 8] = aPre[1];
        if (bn48 < 48)
            *(uint4*)&Bs2h[bn48][bseg] = bPre;
        __syncthreads();

        if (k0 + 32 < D_HID) {
            aPre[0] = *(const uint4*)(g_hidh + (size_t)gr * D_HID + k0 + 32 + aCol);
            aPre[1] = *(const uint4*)(g_hidh + (size_t)gr * D_HID + k0 + 32 + aCol + 8);
            if (bn48 < 48)
                bPre = *(const uint4*)(g_w2t + (size_t)bn48 * D_HID + k0 + 32 + bseg);
        }

#pragma unroll
        for (int ks = 0; ks < 2; ks++) {
            const int kb = ks * 16;
            uint32_t af[2][4], bf[3][2];
#pragma unroll
            for (int i = 0; i < 2; i++) {
                const int m = wm * 32 + i * 16 + g;
                af[i][0] = *(const uint32_t*)&As2h[m][kb + 2 * t];
                af[i][1] = *(const uint32_t*)&As2h[m + 8][kb + 2 * t];
                af[i][2] = *(const uint32_t*)&As2h[m][kb + 2 * t + 8];
                af[i][3] = *(const uint32_t*)&As2h[m + 8][kb + 2 * t + 8];
            }
#pragma unroll
            for (int j = 0; j < 3; j++) {
                const int n = wn * 24 + j * 8 + g;
                bf[j][0] = *(const uint32_t*)&Bs2h[n][kb + 2 * t];
                bf[j][1] = *(const uint32_t*)&Bs2h[n][kb + 2 * t + 8];
            }
#pragma unroll
            for (int i = 0; i < 2; i++)
#pragma unroll
                for (int j = 0; j < 3; j++)
                    mma_f16(acc[i][j], af[i][0], af[i][1], af[i][2], af[i][3],
                            bf[j][0], bf[j][1]);
        }
        __syncthreads();
    }

#pragma unroll
    for (int i = 0; i < 2; i++) {
        const int r0 = bm + wm * 32 + i * 16 + g;
        const int r1 = r0 + 8;
        const float dv0 = (r0 < M) ? __ldg(g_dinv + r0) : 0.f;
        const float dv1 = (r1 < M) ? __ldg(g_dinv + r1) : 0.f;
#pragma unroll
        for (int j = 0; j < 3; j++) {
            const int gc = wn * 24 + j * 8 + 2 * t;
            const float bz0 = __ldg(bias + gc);
            const float bz1 = __ldg(bias + gc + 1);
            if (r0 < M) {
                float2 v = make_float2(acc[i][j][0] + bz0, acc[i][j][1] + bz1);
                *(float2*)(g_h + (size_t)r0 * D_OUT + gc) = v;
                zbuf[(size_t)r0 * (D_OUT / 2) + gc / 2] =
                    __float22half2_rn(make_float2(dv0 * v.x, dv0 * v.y));
            }
            if (r1 < M) {
                float2 v = make_float2(acc[i][j][2] + bz0, acc[i][j][3] + bz1);
                *(float2*)(g_h + (size_t)r1 * D_OUT + gc) = v;
                zbuf[(size_t)r1 * (D_OUT / 2) + gc / 2] =
                    __float22half2_rn(make_float2(dv1 * v.x, dv1 * v.y));
            }
        }
    }
}

// ---------------------------------------------------------------------------
// Graph preprocessing (unchanged from R16)
// ---------------------------------------------------------------------------
__global__ void prep_kernel(const float* __restrict__ W1,
                            const float* __restrict__ W2) {
    int i = blockIdx.x * blockDim.x + threadIdx.x;
    if (i < N_NODES) { g_deg[i] = 0; g_cursor[i] = 0; }
    if (i < W1_ELEMS) {
        const int k = i / D_HID;
        const int n = i % D_HID;
        g_w1t[(size_t)n * D_IN + k] = __float2half(W1[i]);
    }
    if (i < W2_ELEMS) {
        const int k = i / D_OUT;
        const int n = i % D_OUT;
        g_w2t[(size_t)n * D_HID + k] = __float2half(W2[i]);
    }
}

__global__ void convert_idx_kernel(const void* __restrict__ ei_raw) {
    const int* p32 = (const int*)ei_raw;
    bool is64 = true;
#pragma unroll
    for (int i = 0; i < 8; i++) is64 = is64 && (p32[2 * i + 1] == 0);

    int e = blockIdx.x * blockDim.x + threadIdx.x;
    if (e >= N_EDGES) return;
    int s, d;
    if (is64) {
        const long long* p64 = (const long long*)ei_raw;
        s = (int)p64[e];
        d = (int)p64[(size_t)N_EDGES + e];
    } else {
        s = p32[e];
        d = p32[(size_t)N_EDGES + e];
    }
    s = min(max(s, 0), N_NODES - 1);
    d = min(max(d, 0), N_NODES - 1);
    g_src[e] = s;
    g_dst[e] = d;
    atomicAdd(&g_deg[d], 1);
}

__global__ void convert_x_kernel(const float* __restrict__ x) {
    const size_t i = (size_t)(blockIdx.x * blockDim.x + threadIdx.x) * 4;
    if (i >= X_ELEMS) return;
    const float4 v = *(const float4*)(x + i);
    __half2 h0 = __float22half2_rn(make_float2(v.x, v.y));
    __half2 h1 = __float22half2_rn(make_float2(v.z, v.w));
    *(uint2*)(g_xh + i) = make_uint2(*(uint32_t*)&h0, *(uint32_t*)&h1);
}

__global__ __launch_bounds__(256) void blocksum_dinv_kernel() {
    __shared__ int swarp[8];
    const int t = threadIdx.x;
    const int i = blockIdx.x * 256 + t;
    int d = 0;
    if (i < N_NODES) {
        d = g_deg[i];
        g_dinv[i] = rsqrtf((float)(d + 1));   // +1 self-loop
    }
    int v = d;
#pragma unroll
    for (int o = 16; o > 0; o >>= 1) v += __shfl_down_sync(0xffffffffu, v, o);
    if ((t & 31) == 0) swarp[t >> 5] = v;
    __syncthreads();
    if (t == 0) {
        int s = 0;
#pragma unroll
        for (int w = 0; w < 8; w++) s += swarp[w];
        g_bsum[blockIdx.x] = s;
    }
}

__global__ __launch_bounds__(512) void scan_bsums_kernel() {
    __shared__ int sh[512];
    const int t = threadIdx.x;
    sh[t] = (t < NBLK_NODES) ? g_bsum[t] : 0;
    __syncthreads();
#pragma unroll
    for (int off = 1; off < 512; off <<= 1) {
        int v = (t >= off) ? sh[t - off] : 0;
        __syncthreads();
        sh[t] += v;
        __syncthreads();
    }
    if (t < NBLK_NODES) g_bpre[t] = (t == 0) ? 0 : sh[t - 1];
}

__global__ __launch_bounds__(256) void rowptr_kernel() {
    __shared__ int swarp[8];
    const int t = threadIdx.x;
    const int i = blockIdx.x * 256 + t;
    const int lane = t & 31;
    const int w = t >> 5;

    int d = (i < N_NODES) ? g_deg[i] : 0;
    int v = d;
#pragma unroll
    for (int o = 1; o < 32; o <<= 1) {
        int n = __shfl_up_sync(0xffffffffu, v, o);
        if (lane >= o) v += n;
    }
    if (lane == 31) swarp[w] = v;
    __syncthreads();
    if (t == 0) {
        int r = 0;
#pragma unroll
        for (int k = 0; k < 8; k++) { int tmp = swarp[k]; swarp[k] = r; r += tmp; }
    }
    __syncthreads();

    const int excl = g_bpre[blockIdx.x] + swarp[w] + (v - d);
    if (i < N_NODES) {
        g_rowptr[i] = excl;
        if (i == N_NODES - 1) g_rowptr[N_NODES] = excl + d;
    }
}

__global__ void fill_csr_kernel() {
    int e = blockIdx.x * blockDim.x + threadIdx.x;
    if (e >= N_EDGES) return;
    const int s = g_src[e];
    const int d = g_dst[e];
    const int pos = g_rowptr[d] + atomicAdd(&g_cursor[d], 1);
    g_csri[pos] = s;
}

// ---------------------------------------------------------------------------
// Propagation: uint4 gather (unchanged from R16)
// ---------------------------------------------------------------------------
__global__ __launch_bounds__(256) void gather_z_kernel(
    const __half2* __restrict__ z, __half2* __restrict__ nxt,
    float* __restrict__ outf, int last)
{
    const int node = blockIdx.x * 32 + (threadIdx.x >> 3);
    const int lane = threadIdx.x & 7;
    if (node >= N_NODES || lane >= 6) return;   // lanes 6,7 idle

    const int begin = __ldg(&g_rowptr[node]);
    const int end   = __ldg(&g_rowptr[node + 1]);

    const char* zb = (const char*)z;
    const size_t lOff = (size_t)lane * 16;

    float2 s0 = make_float2(0.f, 0.f);
    float2 s1 = make_float2(0.f, 0.f);
    float2 s2 = make_float2(0.f, 0.f);
    float2 s3 = make_float2(0.f, 0.f);

    int e = begin;
    for (; e + 2 <= end; e += 2) {
        const int srcA = __ldg(&g_csri[e]);
        const int srcB = __ldg(&g_csri[e + 1]);
        const uint4 va = __ldg((const uint4*)(zb + (size_t)srcA * 96 + lOff));
        const uint4 vb = __ldg((const uint4*)(zb + (size_t)srcB * 96 + lOff));
        const __half2* ha = (const __half2*)&va;
        const __half2* hb = (const __half2*)&vb;
        float2 f;
        f = __half22float2(ha[0]); s0.x += f.x; s0.y += f.y;
        f = __half22float2(ha[1]); s1.x += f.x; s1.y += f.y;
        f = __half22float2(ha[2]); s2.x += f.x; s2.y += f.y;
        f = __half22float2(ha[3]); s3.x += f.x; s3.y += f.y;
        f = __half22float2(hb[0]); s0.x += f.x; s0.y += f.y;
        f = __half22float2(hb[1]); s1.x += f.x; s1.y += f.y;
        f = __half22float2(hb[2]); s2.x += f.x; s2.y += f.y;
        f = __half22float2(hb[3]); s3.x += f.x; s3.y += f.y;
    }
    if (e < end) {
        const int src = __ldg(&g_csri[e]);
        const uint4 v = __ldg((const uint4*)(zb + (size_t)src * 96 + lOff));
        const __half2* hv = (const __half2*)&v;
        float2 f;
        f = __half22float2(hv[0]); s0.x += f.x; s0.y += f.y;
        f = __half22float2(hv[1]); s1.x += f.x; s1.y += f.y;
        f = __half22float2(hv[2]); s2.x += f.x; s2.y += f.y;
        f = __half22float2(hv[3]); s3.x += f.x; s3.y += f.y;
    }

    {   // self-loop contribution
        const uint4 v = *(const uint4*)(zb + (size_t)node * 96 + lOff);
        const __half2* hv = (const __half2*)&v;
        float2 f;
        f = __half22float2(hv[0]); s0.x += f.x; s0.y += f.y;
        f = __half22float2(hv[1]); s1.x += f.x; s1.y += f.y;
        f = __half22float2(hv[2]); s2.x += f.x; s2.y += f.y;
        f = __half22float2(hv[3]); s3.x += f.x; s3.y += f.y;
    }

    const float di = __ldg(&g_dinv[node]);
    const float* ph = g_h + (size_t)node * D_OUT + lane * 8;
    const float4 hA = *(const float4*)(ph);
    const float4 hB = *(const float4*)(ph + 4);

    const float w = (1.0f - ALPHA) * di;
    float4 oA, oB;
    oA.x = w * s0.x + ALPHA * hA.x;  oA.y = w * s0.y + ALPHA * hA.y;
    oA.z = w * s1.x + ALPHA * hA.z;  oA.w = w * s1.y + ALPHA * hA.w;
    oB.x = w * s2.x + ALPHA * hB.x;  oB.y = w * s2.y + ALPHA * hB.y;
    oB.z = w * s3.x + ALPHA * hB.z;  oB.w = w * s3.y + ALPHA * hB.w;

    if (last) {
        float* po = outf + (size_t)node * D_OUT + lane * 8;
        *(float4*)(po)     = oA;
        *(float4*)(po + 4) = oB;
    } else {
        uint4 pk;
        __half2* hp = (__half2*)&pk;
        hp[0] = __float22half2_rn(make_float2(di * oA.x, di * oA.y));
        hp[1] = __float22half2_rn(make_float2(di * oA.z, di * oA.w));
        hp[2] = __float22half2_rn(make_float2(di * oB.x, di * oB.y));
        hp[3] = __float22half2_rn(make_float2(di * oB.z, di * oB.w));
        *(uint4*)((char*)nxt + (size_t)node * 96 + lOff) = pk;
    }
}

// ---------------------------------------------------------------------------
// Launch. Inputs matched by element count. gemm1 stays at launch slot 3.
// ---------------------------------------------------------------------------
extern "C" void kernel_launch(void* const* d_in, const int* in_sizes, int n_in,
                              void* d_out, int out_size)
{
    const void* x = nullptr; const void* ei = nullptr;
    const void* W1 = nullptr; const void* b1 = nullptr;
    const void* W2 = nullptr; const void* b2 = nullptr;

    for (int i = 0; i < n_in; i++) {
        switch (in_sizes[i]) {
            case 25600000: x  = d_in[i]; break;
            case  3200000: ei = d_in[i]; break;
            case   131072: W1 = d_in[i]; break;
            case      512: b1 = d_in[i]; break;
            case    24576: W2 = d_in[i]; break;
            case       48: b2 = d_in[i]; break;
            default: break;
        }
    }
    if (!x)  x  = d_in[0];
    if (!ei) ei = d_in[1];
    if (!W1) W1 = d_in[2];
    if (!b1) b1 = d_in[3];
    if (!W2) W2 = d_in[4];
    if (!b2) b2 = d_in[5];

    float* out = (float*)d_out;
    const int M = N_NODES;

    __half2* zA;  cudaGetSymbolAddress((void**)&zA, g_zA);
    __half2* zB;  cudaGetSymbolAddress((void**)&zB, g_zB);

    static int smem_set = 0;
    if (!smem_set) {
        cudaFuncSetAttribute(gemm1_tc_kernel,
                             cudaFuncAttributeMaxDynamicSharedMemorySize, G1_SMEM);
        smem_set = 1;
    }

    // 0: zero deg/cursor + W1/W2 fp16 transposes (before convert_idx!)
    prep_kernel<<<(W1_ELEMS + 255) / 256, 256>>>((const float*)W1,
                                                 (const float*)W2);
    // 1: index convert + degree accumulate (fused)
    convert_idx_kernel<<<(N_EDGES + 255) / 256, 256>>>(ei);
    // 2: x -> fp16
    convert_x_kernel<<<(int)((X_ELEMS / 4 + 255) / 256), 256>>>((const float*)x);

    // 3: GEMM1 fp16 + ldmatrix (target of the ncu capture at launch index 3)
    {
        dim3 grid(D_HID / 128, (M + 127) / 128);
        gemm1_tc_kernel<<<grid, 256, G1_SMEM>>>((const float*)b1, M);
    }

    // 4-6: full-chip scan -> rowptr (+dinv folded into pass A)
    blocksum_dinv_kernel<<<NBLK_NODES, 256>>>();
    scan_bsums_kernel<<<1, 512>>>();
    rowptr_kernel<<<NBLK_NODES, 256>>>();

    // 7: CSR fill (src only)
    fill_csr_kernel<<<(N_EDGES + 255) / 256, 256>>>();

    // 8: GEMM2 fp16 (writes g_h = h fp32 and zA = half2(dinv*h))
    {
        dim3 grid((M + 127) / 128);
        gemm2_tc_kernel<<<grid, 256>>>((const float*)b2, zA, M);
    }

    // 9..18: 10 propagation steps on fp16 z; last step emits fp32 out.
    const int gblocks = (N_NODES + 31) / 32;
    __half2* cur = zA;
    __half2* nxt = zB;
    for (int s = 0; s < K_STEPS; s++) {
        gather_z_kernel<<<gblocks, 256>>>(cur, nxt, out, s == K_STEPS - 1 ? 1 : 0);
        __half2* tmp = cur; cur = nxt; nxt = tmp;
    }
}